// round 5
// baseline (speedup 1.0000x reference)
#include <cuda_runtime.h>
#include <cuda_bf16.h>
#include <math.h>
#include <stdint.h>

// ---------------------------------------------------------------------------
// GSSM — mma.sync (HMMA) bf16-split implementation, round 5:
//  - 512 threads / 16 warps per CTA (4 warps per SMSP scheduler) to hide
//    LDSM latency and sync boundaries that left the tensor pipe 50% idle
//  - warp tile 32t x 16m x 3w (acc 48 regs), same total MMA count
//
// Inputs (metadata order):
//  0: x(32,2048,512) 1: W_theta(512,64) 2: b_theta(64)
//  3: W_lam(512,1024) 4: b_lam 5: W_delt 6: b_delt 7: W_inp 8: b_inp
//  9: W_par(128,2) 10: b_par(2) 11: W_add(1024,1) 12: b_add(1)
// Output: parity_logits (32,2) at [0,64), add_pred (32,1) at [64,96)
// ---------------------------------------------------------------------------

#define B_ 32
#define T_ 2048
#define DIN_ 512
#define M_ 1024
#define K_ 64

#define TB 128               // t rows per CTA
#define MB 64                // m cols per CTA
#define KC 32                // k per chunk
#define NKC (DIN_ / KC)      // 16 chunks
#define NTT2 (T_ / TB)       // 16 t-tiles per batch
#define NMB (M_ / MB)        // 16 m-tiles

#define NTHREADS 512

// smem stage layout (bf16, padded rows of 40 elems = 80 B):
//   A: [2 split][128 rows][40]  = 20480 B
//   B: [6 w*s  ][ 64 rows][40]  = 30720 B
#define A_ROW_B 80
#define STAGE_A 20480
#define STAGE_BYTES 51200
#define NSTAGES 3
#define SMEM_BYTES (STAGE_BYTES * NSTAGES)   // 153600

// ---- static device scratch (no allocation allowed) ------------------------
__device__ __nv_bfloat16 g_xhi[(size_t)B_ * T_ * DIN_];
__device__ __nv_bfloat16 g_xlo[(size_t)B_ * T_ * DIN_];
__device__ __nv_bfloat16 g_wthi[3u * M_ * DIN_];   // [w][m][k] K-major
__device__ __nv_bfloat16 g_wtlo[3u * M_ * DIN_];
__device__ float g_A[B_ * NTT2 * M_];
__device__ float g_D[B_ * NTT2 * M_];
__device__ float g_xs[B_ * DIN_];

// ---- helpers ---------------------------------------------------------------
__device__ __forceinline__ uint32_t smem_u32(const void* p) {
    uint32_t a;
    asm("{ .reg .u64 t; cvta.to.shared.u64 t, %1; cvt.u32.u64 %0, t; }"
        : "=r"(a) : "l"(p));
    return a;
}

__device__ __forceinline__ void cp_async16(uint32_t dst, const void* src) {
    asm volatile("cp.async.cg.shared.global [%0], [%1], 16;"
                 :: "r"(dst), "l"(src) : "memory");
}

__device__ __forceinline__ void ldsm_x4(uint32_t* r, uint32_t addr) {
    asm volatile("ldmatrix.sync.aligned.m8n8.x4.shared.b16 {%0,%1,%2,%3}, [%4];"
                 : "=r"(r[0]), "=r"(r[1]), "=r"(r[2]), "=r"(r[3]) : "r"(addr));
}

__device__ __forceinline__ void mma16816(float* d, const uint32_t* a,
                                         const uint32_t* b) {
    asm volatile(
        "mma.sync.aligned.m16n8k16.row.col.f32.bf16.bf16.f32 "
        "{%0,%1,%2,%3}, {%4,%5,%6,%7}, {%8,%9}, {%0,%1,%2,%3};"
        : "+f"(d[0]), "+f"(d[1]), "+f"(d[2]), "+f"(d[3])
        : "r"(a[0]), "r"(a[1]), "r"(a[2]), "r"(a[3]), "r"(b[0]), "r"(b[1]));
}

__device__ __forceinline__ float softplus_f(float z) {
    return fmaxf(z, 0.0f) + log1pf(expf(-fabsf(z)));
}

// ---------------------------------------------------------------------------
// Prep 1: split x -> bf16 hi/lo
// ---------------------------------------------------------------------------
__global__ void xsplit_kernel(const float* __restrict__ x) {
    size_t i = ((size_t)blockIdx.x * 256 + threadIdx.x) * 8;
    float4 v0 = *(const float4*)(x + i);
    float4 v1 = *(const float4*)(x + i + 4);
    float f[8] = {v0.x, v0.y, v0.z, v0.w, v1.x, v1.y, v1.z, v1.w};
    __align__(16) __nv_bfloat16 h[8];
    __align__(16) __nv_bfloat16 l[8];
#pragma unroll
    for (int j = 0; j < 8; ++j) {
        h[j] = __float2bfloat16(f[j]);
        l[j] = __float2bfloat16(f[j] - __bfloat162float(h[j]));
    }
    *(uint4*)&g_xhi[i] = *(const uint4*)h;
    *(uint4*)&g_xlo[i] = *(const uint4*)l;
}

// ---------------------------------------------------------------------------
// Prep 2: transpose + split W (512x1024 f32) -> [w][m][k] bf16 hi/lo
// ---------------------------------------------------------------------------
__global__ void wtsplit_kernel(const float* __restrict__ Wl,
                               const float* __restrict__ Wd,
                               const float* __restrict__ Wi) {
    __shared__ float tile[32][33];
    const int w = blockIdx.z;
    const float* W = (w == 0) ? Wl : ((w == 1) ? Wd : Wi);
    const int m0 = blockIdx.x * 32;
    const int k0 = blockIdx.y * 32;
    const int tx = threadIdx.x & 31;
    const int ty = threadIdx.x >> 5;
#pragma unroll
    for (int r = 0; r < 4; ++r)
        tile[ty + 8 * r][tx] = W[(size_t)(k0 + ty + 8 * r) * M_ + m0 + tx];
    __syncthreads();
#pragma unroll
    for (int r = 0; r < 4; ++r) {
        int m = ty + 8 * r;
        int k = tx;
        float v = tile[k][m];
        __nv_bfloat16 h = __float2bfloat16(v);
        __nv_bfloat16 lo = __float2bfloat16(v - __bfloat162float(h));
        size_t o = ((size_t)w * M_ + m0 + m) * DIN_ + k0 + k;
        g_wthi[o] = h;
        g_wtlo[o] = lo;
    }
}

// ---------------------------------------------------------------------------
// Kernel A: xs[b,d] = sum_t x[b,t,d]   (fp64 accumulation; parity branch)
// ---------------------------------------------------------------------------
__global__ void xs_kernel(const float* __restrict__ x) {
    int b = blockIdx.y;
    int d = blockIdx.x * 128 + threadIdx.x;
    const float* xp = x + (size_t)b * T_ * DIN_ + d;
    double a0 = 0.0, a1 = 0.0, a2 = 0.0, a3 = 0.0;
    for (int t = 0; t < T_; t += 4) {
        a0 += (double)xp[(size_t)(t + 0) * DIN_];
        a1 += (double)xp[(size_t)(t + 1) * DIN_];
        a2 += (double)xp[(size_t)(t + 2) * DIN_];
        a3 += (double)xp[(size_t)(t + 3) * DIN_];
    }
    g_xs[b * DIN_ + d] = (float)((a0 + a1) + (a2 + a3));
}

// ---------------------------------------------------------------------------
// Main kernel: HMMA split-bf16 triple-GEMM + fused softplus/exp + t-scan.
// grid (16 m-tiles, 512 bt-tiles), 512 threads (16 warps: 4 t x 4 m).
// ---------------------------------------------------------------------------
__global__ void __launch_bounds__(NTHREADS, 1)
gssm_mma_kernel(const float* __restrict__ b_lam,
                const float* __restrict__ b_delt,
                const float* __restrict__ b_inp) {
    extern __shared__ __align__(128) char smem[];
    const uint32_t sb = smem_u32(smem);
    const int tid = threadIdx.x;
    const int lane = tid & 31;
    const int wid = tid >> 5;
    const int wt = wid & 3;        // t-quadrant: rows wt*32..+31
    const int wm = wid >> 2;       // m-sixteenth: cols wm*16..+15
    const int mb = blockIdx.x;
    const int tb = blockIdx.y;     // b*16 + tt
    const int m0 = mb * MB;
    const int r0 = tb * TB;

    // ---- hoisted cp.async source pointers / dest offsets -------------------
    // A: 1024 x 16B over 512 threads (2 each); B: 1536 x 16B (3 each)
    const __nv_bfloat16* srcA[2];
    uint32_t dstA[2];
#pragma unroll
    for (int q = 0; q < 2; ++q) {
        int idx = q * NTHREADS + tid;
        int split = idx >> 9;
        int r = (idx >> 2) & 127;
        int v = idx & 3;
        srcA[q] = (split ? g_xlo : g_xhi) + (size_t)(r0 + r) * DIN_ + v * 8;
        dstA[q] = sb + split * 10240 + r * A_ROW_B + v * 16;
    }
    const __nv_bfloat16* srcB[3];
    uint32_t dstB[3];
#pragma unroll
    for (int q = 0; q < 3; ++q) {
        int idx = q * NTHREADS + tid;
        int ws = idx >> 8;
        int w = ws >> 1, s = ws & 1;
        int n = (idx >> 2) & 63;
        int v = idx & 3;
        srcB[q] = (s ? g_wtlo : g_wthi) + ((size_t)w * M_ + m0 + n) * DIN_ + v * 8;
        dstB[q] = sb + STAGE_A + ws * 5120 + n * A_ROW_B + v * 16;
    }

    // ---- hoisted ldmatrix row offsets --------------------------------------
    const int rsub = (lane & 7) + 8 * ((lane >> 3) & 1);
    const int ksub2 = 16 * (lane >> 4);           // ksub * 2 bytes
    uint32_t aRow[2];
#pragma unroll
    for (int ts = 0; ts < 2; ++ts)
        aRow[ts] = (uint32_t)((wt * 32 + ts * 16 + rsub) * A_ROW_B) + ksub2;
    const uint32_t bRow =
        (uint32_t)(STAGE_A + (wm * 16 + rsub) * A_ROW_B) + ksub2;

    float acc[3][2][2][4];
#pragma unroll
    for (int w = 0; w < 3; ++w)
#pragma unroll
        for (int ts = 0; ts < 2; ++ts)
#pragma unroll
            for (int nt = 0; nt < 2; ++nt)
#pragma unroll
                for (int f = 0; f < 4; ++f) acc[w][ts][nt][f] = 0.f;

    auto issue_load = [&](int ic, int stg) {
        const uint32_t so = stg * STAGE_BYTES;
        const size_t ko = (size_t)ic * KC;
#pragma unroll
        for (int q = 0; q < 2; ++q) cp_async16(dstA[q] + so, srcA[q] + ko);
#pragma unroll
        for (int q = 0; q < 3; ++q) cp_async16(dstB[q] + so, srcB[q] + ko);
        asm volatile("cp.async.commit_group;" ::: "memory");
    };

    auto compute = [&](int stg) {
        const uint32_t base = sb + stg * STAGE_BYTES;
#pragma unroll
        for (int kk = 0; kk < 2; ++kk) {
            const uint32_t kb = base + kk * 32;
            uint32_t ah[2][4], al[2][4];
#pragma unroll
            for (int ts = 0; ts < 2; ++ts) {
                ldsm_x4(ah[ts], kb + aRow[ts]);
                ldsm_x4(al[ts], kb + 10240 + aRow[ts]);
            }
            // B: one ldsm_x4 per (w,s) covers n16 x k16:
            //   r4[0]=n0 k0, r4[1]=n1 k0, r4[2]=n0 k1, r4[3]=n1 k1
            uint32_t bf[6][2][2];
#pragma unroll
            for (int ws = 0; ws < 6; ++ws) {
                uint32_t r4[4];
                ldsm_x4(r4, kb + ws * 5120 + bRow);
                bf[ws][0][0] = r4[0];
                bf[ws][1][0] = r4[1];
                bf[ws][0][1] = r4[2];
                bf[ws][1][1] = r4[3];
            }
            // product-outer ordering: 12 independent MMAs between RAW reuses
#pragma unroll
            for (int pr = 0; pr < 3; ++pr) {
#pragma unroll
                for (int w = 0; w < 3; ++w)
#pragma unroll
                    for (int ts = 0; ts < 2; ++ts)
#pragma unroll
                        for (int nt = 0; nt < 2; ++nt) {
                            const uint32_t* af = (pr == 1) ? al[ts] : ah[ts];
                            const uint32_t* bb =
                                bf[2 * w + (pr == 2 ? 1 : 0)][nt];
                            mma16816(acc[w][ts][nt], af, bb);
                        }
            }
        }
    };

    issue_load(0, 0);
    issue_load(1, 1);
#pragma unroll 1
    for (int ic = 0; ic < NKC; ++ic) {
        if (ic < NKC - 1)
            asm volatile("cp.async.wait_group 1;" ::: "memory");
        else
            asm volatile("cp.async.wait_group 0;" ::: "memory");
        __syncthreads();
        if (ic + 2 < NKC) issue_load(ic + 2, (ic + 2) % NSTAGES);
        compute(ic % NSTAGES);
    }
    __syncthreads();   // all compute done before smem reuse by epilogue

    // ---- fused epilogue: bias + softplus + exp, then t-scan ----
    float* salpha = (float*)smem;                      // [128][66]
    float* sdrive = (float*)(smem + 33792);            // [128][66]
    float* sAp = (float*)(smem + 67584);               // [8][64]
    float* sDp = (float*)(smem + 67584 + 2048);        // [8][64]

#pragma unroll
    for (int ts = 0; ts < 2; ++ts) {
#pragma unroll
        for (int nt = 0; nt < 2; ++nt) {
            const int mloc = wm * 16 + nt * 8 + 2 * (lane & 3);
            const float2 bl = *(const float2*)&b_lam[m0 + mloc];
            const float2 bd = *(const float2*)&b_delt[m0 + mloc];
            const float2 bi = *(const float2*)&b_inp[m0 + mloc];
#pragma unroll
            for (int h = 0; h < 2; ++h) {
                const int t = wt * 32 + ts * 16 + h * 8 + (lane >> 2);
#pragma unroll
                for (int c = 0; c < 2; ++c) {
                    float zl = acc[0][ts][nt][h * 2 + c] + (c ? bl.y : bl.x);
                    float zd = acc[1][ts][nt][h * 2 + c] + (c ? bd.y : bd.x);
                    float zi = acc[2][ts][nt][h * 2 + c] + (c ? bi.y : bi.x);
                    float lamv = softplus_f(zl);
                    float dlv = softplus_f(zd);
                    salpha[t * 66 + mloc + c] = expf(-dlv * lamv);
                    sdrive[t * 66 + mloc + c] = dlv * zi;
                }
            }
        }
    }
    __syncthreads();
    {
        const int m = tid & 63;
        const int ty = tid >> 6;     // 0..7, each 16 t's
        float A = 1.f, D = 0.f;
#pragma unroll
        for (int r = 0; r < 16; ++r) {
            int t = ty * 16 + r;
            float a = salpha[t * 66 + m];
            D = a * D + sdrive[t * 66 + m];
            A *= a;
        }
        sAp[ty * 64 + m] = A;
        sDp[ty * 64 + m] = D;
    }
    __syncthreads();
    if (tid < 64) {
        float A = 1.f, D = 0.f;
#pragma unroll
        for (int r = 0; r < 8; ++r) {
            float a = sAp[r * 64 + tid];
            D = a * D + sDp[r * 64 + tid];
            A *= a;
        }
        size_t o = (size_t)tb * M_ + m0 + tid;
        g_A[o] = A;
        g_D[o] = D;
    }
}

// ---------------------------------------------------------------------------
// Kernel C: combine 16 t-tiles per (b,m), then add_pred[b] = s . W_add + b_add
// ---------------------------------------------------------------------------
__global__ void combine_kernel(const float* __restrict__ W_add,
                               const float* __restrict__ b_add,
                               float* __restrict__ out) {
    int b = blockIdx.x;
    int m = threadIdx.x;
    float s = 0.f;
#pragma unroll
    for (int tt = 0; tt < NTT2; ++tt) {
        size_t idx = ((size_t)(b * NTT2 + tt)) * M_ + m;
        s = g_A[idx] * s + g_D[idx];
    }
    float v = s * W_add[m];
    __shared__ float red[32];
    for (int off = 16; off > 0; off >>= 1)
        v += __shfl_down_sync(0xffffffffu, v, off);
    if ((m & 31) == 0) red[m >> 5] = v;
    __syncthreads();
    if (m < 32) {
        float w = red[m];
        for (int off = 16; off > 0; off >>= 1)
            w += __shfl_down_sync(0xffffffffu, w, off);
        if (m == 0) out[2 * B_ + b] = w + b_add[0];
    }
}

// ---------------------------------------------------------------------------
// Kernel P: parity path (fp64 angle accumulation)
// ---------------------------------------------------------------------------
__global__ void parity_kernel(const float* __restrict__ W_theta,
                              const float* __restrict__ b_theta,
                              const float* __restrict__ W_par,
                              const float* __restrict__ b_par,
                              float* __restrict__ out) {
    int b = blockIdx.x;
    int k = threadIdx.x;
    double acc = 0.0;
    const float* xsb = &g_xs[b * DIN_];
    for (int d = 0; d < DIN_; ++d)
        acc += (double)xsb[d] * (double)W_theta[d * K_ + k];
    acc += (double)T_ * (double)b_theta[k];
    double ang = 3.14159265358979323846 * acc;
    double sn, cs;
    sincos(ang, &sn, &cs);
    __shared__ float g[2 * K_];
    g[k] = (float)cs;
    g[K_ + k] = (float)sn;
    __syncthreads();
    if (k < 2) {
        float l = b_par[k];
        for (int j = 0; j < 2 * K_; ++j)
            l += g[j] * W_par[j * 2 + k];
        out[b * 2 + k] = l;
    }
}

// ---------------------------------------------------------------------------
extern "C" void kernel_launch(void* const* d_in, const int* in_sizes, int n_in,
                              void* d_out, int out_size) {
    const float* x       = (const float*)d_in[0];
    const float* W_theta = (const float*)d_in[1];
    const float* b_theta = (const float*)d_in[2];
    const float* W_lam   = (const float*)d_in[3];
    const float* b_lam   = (const float*)d_in[4];
    const float* W_delt  = (const float*)d_in[5];
    const float* b_delt  = (const float*)d_in[6];
    const float* W_inp   = (const float*)d_in[7];
    const float* b_inp   = (const float*)d_in[8];
    const float* W_par   = (const float*)d_in[9];
    const float* b_par   = (const float*)d_in[10];
    const float* W_add   = (const float*)d_in[11];
    const float* b_add   = (const float*)d_in[12];
    float* out = (float*)d_out;

    static int smem_set = 0;
    if (!smem_set) {
        cudaFuncSetAttribute(gssm_mma_kernel,
                             cudaFuncAttributeMaxDynamicSharedMemorySize,
                             SMEM_BYTES);
        smem_set = 1;
    }

    // Prep: split/convert inputs
    xsplit_kernel<<<((size_t)B_ * T_ * DIN_) / (256 * 8), 256>>>(x);
    wtsplit_kernel<<<dim3(32, 16, 3), 256>>>(W_lam, W_delt, W_inp);
    xs_kernel<<<dim3(DIN_ / 128, B_), 128>>>(x);

    // Main fused tensor-core GEMM + scan-reduce
    gssm_mma_kernel<<<dim3(NMB, B_ * NTT2), NTHREADS, SMEM_BYTES>>>(
        b_lam, b_delt, b_inp);

    // Heads
    parity_kernel<<<B_, K_>>>(W_theta, b_theta, W_par, b_par, out);
    combine_kernel<<<B_, M_>>>(W_add, b_add, out);
}

// round 6
// speedup vs baseline: 1.3238x; 1.3238x over previous
#include <cuda_runtime.h>
#include <cuda_fp16.h>
#include <math.h>
#include <stdint.h>

// ---------------------------------------------------------------------------
// GSSM — mma.sync (HMMA) fp16 2-product split, round 6.
// Empirical finding (R3-R5): legacy mma.sync throughput is a hard ceiling
// proportional to HMMA instruction count (tensor pipe pegged at ~50% =
// saturation for this op across 3 very different kernels). So: reduce the
// instruction count. fp16 has 11 mantissa bits; x is kept as x_hi+x_lo
// (22 bits ~ fp32), w rounded once to fp16. z = (x_hi + x_lo)*w_hi needs
// only 2 products (was 3 with bf16), and only one W operand array.
//
// Inputs (metadata order):
//  0: x(32,2048,512) 1: W_theta(512,64) 2: b_theta(64)
//  3: W_lam(512,1024) 4: b_lam 5: W_delt 6: b_delt 7: W_inp 8: b_inp
//  9: W_par(128,2) 10: b_par(2) 11: W_add(1024,1) 12: b_add(1)
// Output: parity_logits (32,2) at [0,64), add_pred (32,1) at [64,96)
// ---------------------------------------------------------------------------

#define B_ 32
#define T_ 2048
#define DIN_ 512
#define M_ 1024
#define K_ 64

#define TB 128               // t rows per CTA
#define MB 64                // m cols per CTA
#define KC 32                // k per chunk
#define NKC (DIN_ / KC)      // 16 chunks
#define NTT2 (T_ / TB)       // 16 t-tiles per batch
#define NMB (M_ / MB)        // 16 m-tiles

#define NTHREADS 512

// smem stage layout (fp16, padded rows of 40 elems = 80 B):
//   A: [2 split][128 rows][40]  = 20480 B
//   B: [3 w    ][ 64 rows][40]  = 15360 B
#define A_ROW_B 80
#define A_SPLIT_B 10240
#define STAGE_A 20480
#define STAGE_BYTES 35840
#define NSTAGES 3
#define SMEM_BYTES (STAGE_BYTES * NSTAGES)   // 107520

// ---- static device scratch (no allocation allowed) ------------------------
__device__ __half g_xhi[(size_t)B_ * T_ * DIN_];
__device__ __half g_xlo[(size_t)B_ * T_ * DIN_];
__device__ __half g_wh[3u * M_ * DIN_];    // [w][m][k] K-major, fp16
__device__ float g_A[B_ * NTT2 * M_];
__device__ float g_D[B_ * NTT2 * M_];
__device__ float g_xs[B_ * DIN_];

// ---- helpers ---------------------------------------------------------------
__device__ __forceinline__ uint32_t smem_u32(const void* p) {
    uint32_t a;
    asm("{ .reg .u64 t; cvta.to.shared.u64 t, %1; cvt.u32.u64 %0, t; }"
        : "=r"(a) : "l"(p));
    return a;
}

__device__ __forceinline__ void cp_async16(uint32_t dst, const void* src) {
    asm volatile("cp.async.cg.shared.global [%0], [%1], 16;"
                 :: "r"(dst), "l"(src) : "memory");
}

__device__ __forceinline__ void ldsm_x4(uint32_t* r, uint32_t addr) {
    asm volatile("ldmatrix.sync.aligned.m8n8.x4.shared.b16 {%0,%1,%2,%3}, [%4];"
                 : "=r"(r[0]), "=r"(r[1]), "=r"(r[2]), "=r"(r[3]) : "r"(addr));
}

__device__ __forceinline__ void mma16816(float* d, const uint32_t* a,
                                         const uint32_t* b) {
    asm volatile(
        "mma.sync.aligned.m16n8k16.row.col.f32.f16.f16.f32 "
        "{%0,%1,%2,%3}, {%4,%5,%6,%7}, {%8,%9}, {%0,%1,%2,%3};"
        : "+f"(d[0]), "+f"(d[1]), "+f"(d[2]), "+f"(d[3])
        : "r"(a[0]), "r"(a[1]), "r"(a[2]), "r"(a[3]), "r"(b[0]), "r"(b[1]));
}

__device__ __forceinline__ float softplus_f(float z) {
    return fmaxf(z, 0.0f) + log1pf(expf(-fabsf(z)));
}

// ---------------------------------------------------------------------------
// Prep 1: split x -> fp16 hi/lo (hi+lo carries ~22 mantissa bits)
// ---------------------------------------------------------------------------
__global__ void xsplit_kernel(const float* __restrict__ x) {
    size_t i = ((size_t)blockIdx.x * 256 + threadIdx.x) * 8;
    float4 v0 = *(const float4*)(x + i);
    float4 v1 = *(const float4*)(x + i + 4);
    float f[8] = {v0.x, v0.y, v0.z, v0.w, v1.x, v1.y, v1.z, v1.w};
    __align__(16) __half h[8];
    __align__(16) __half l[8];
#pragma unroll
    for (int j = 0; j < 8; ++j) {
        h[j] = __float2half(f[j]);
        l[j] = __float2half(f[j] - __half2float(h[j]));
    }
    *(uint4*)&g_xhi[i] = *(const uint4*)h;
    *(uint4*)&g_xlo[i] = *(const uint4*)l;
}

// ---------------------------------------------------------------------------
// Prep 2: transpose W (512x1024 f32) -> [w][m][k] fp16
// ---------------------------------------------------------------------------
__global__ void wtsplit_kernel(const float* __restrict__ Wl,
                               const float* __restrict__ Wd,
                               const float* __restrict__ Wi) {
    __shared__ float tile[32][33];
    const int w = blockIdx.z;
    const float* W = (w == 0) ? Wl : ((w == 1) ? Wd : Wi);
    const int m0 = blockIdx.x * 32;
    const int k0 = blockIdx.y * 32;
    const int tx = threadIdx.x & 31;
    const int ty = threadIdx.x >> 5;
#pragma unroll
    for (int r = 0; r < 4; ++r)
        tile[ty + 8 * r][tx] = W[(size_t)(k0 + ty + 8 * r) * M_ + m0 + tx];
    __syncthreads();
#pragma unroll
    for (int r = 0; r < 4; ++r) {
        int m = ty + 8 * r;
        int k = tx;
        size_t o = ((size_t)w * M_ + m0 + m) * DIN_ + k0 + k;
        g_wh[o] = __float2half(tile[k][m]);
    }
}

// ---------------------------------------------------------------------------
// Kernel A: xs[b,d] = sum_t x[b,t,d]   (fp64 accumulation; parity branch)
// ---------------------------------------------------------------------------
__global__ void xs_kernel(const float* __restrict__ x) {
    int b = blockIdx.y;
    int d = blockIdx.x * 128 + threadIdx.x;
    const float* xp = x + (size_t)b * T_ * DIN_ + d;
    double a0 = 0.0, a1 = 0.0, a2 = 0.0, a3 = 0.0;
    for (int t = 0; t < T_; t += 4) {
        a0 += (double)xp[(size_t)(t + 0) * DIN_];
        a1 += (double)xp[(size_t)(t + 1) * DIN_];
        a2 += (double)xp[(size_t)(t + 2) * DIN_];
        a3 += (double)xp[(size_t)(t + 3) * DIN_];
    }
    g_xs[b * DIN_ + d] = (float)((a0 + a1) + (a2 + a3));
}

// ---------------------------------------------------------------------------
// Main kernel: HMMA fp16 2-product triple-GEMM + fused softplus/exp + t-scan.
// grid (16 m-tiles, 512 bt-tiles), 512 threads (16 warps: 4 t x 4 m).
// ---------------------------------------------------------------------------
__global__ void __launch_bounds__(NTHREADS, 1)
gssm_mma_kernel(const float* __restrict__ b_lam,
                const float* __restrict__ b_delt,
                const float* __restrict__ b_inp) {
    extern __shared__ __align__(128) char smem[];
    const uint32_t sb = smem_u32(smem);
    const int tid = threadIdx.x;
    const int lane = tid & 31;
    const int wid = tid >> 5;
    const int wt = wid & 3;        // t-quadrant: rows wt*32..+31
    const int wm = wid >> 2;       // m-sixteenth: cols wm*16..+15
    const int mb = blockIdx.x;
    const int tb = blockIdx.y;     // b*16 + tt
    const int m0 = mb * MB;
    const int r0 = tb * TB;

    // ---- hoisted cp.async source pointers / dest offsets -------------------
    // A: 1024 x 16B over 512 threads (2 each); B: 768 x 16B (1.5 each)
    const __half* srcA[2];
    uint32_t dstA[2];
#pragma unroll
    for (int q = 0; q < 2; ++q) {
        int idx = q * NTHREADS + tid;
        int split = idx >> 9;
        int r = (idx >> 2) & 127;
        int v = idx & 3;
        srcA[q] = (split ? g_xlo : g_xhi) + (size_t)(r0 + r) * DIN_ + v * 8;
        dstA[q] = sb + split * A_SPLIT_B + r * A_ROW_B + v * 16;
    }
    const __half* srcB[2];
    uint32_t dstB[2];
#pragma unroll
    for (int q = 0; q < 2; ++q) {
        int idx = q * NTHREADS + tid;          // q=1 valid only for tid<256
        int w = idx >> 8;                       // 0..2
        int n = (idx >> 2) & 63;
        int v = idx & 3;
        if (w > 2) w = 2;                       // clamp (unused lanes predicated)
        srcB[q] = g_wh + ((size_t)w * M_ + m0 + n) * DIN_ + v * 8;
        dstB[q] = sb + STAGE_A + w * 5120 + n * A_ROW_B + v * 16;
    }
    const bool b1_active = (tid < 256);

    // ---- hoisted ldmatrix row offsets --------------------------------------
    const int rsub = (lane & 7) + 8 * ((lane >> 3) & 1);
    const int ksub2 = 16 * (lane >> 4);           // ksub * 2 bytes
    uint32_t aRow[2];
#pragma unroll
    for (int ts = 0; ts < 2; ++ts)
        aRow[ts] = (uint32_t)((wt * 32 + ts * 16 + rsub) * A_ROW_B) + ksub2;
    const uint32_t bRow =
        (uint32_t)(STAGE_A + (wm * 16 + rsub) * A_ROW_B) + ksub2;

    float acc[3][2][2][4];
#pragma unroll
    for (int w = 0; w < 3; ++w)
#pragma unroll
        for (int ts = 0; ts < 2; ++ts)
#pragma unroll
            for (int nt = 0; nt < 2; ++nt)
#pragma unroll
                for (int f = 0; f < 4; ++f) acc[w][ts][nt][f] = 0.f;

    auto issue_load = [&](int ic, int stg) {
        const uint32_t so = stg * STAGE_BYTES;
        const size_t ko = (size_t)ic * KC;
        cp_async16(dstA[0] + so, srcA[0] + ko);
        cp_async16(dstA[1] + so, srcA[1] + ko);
        cp_async16(dstB[0] + so, srcB[0] + ko);
        if (b1_active) cp_async16(dstB[1] + so, srcB[1] + ko);
        asm volatile("cp.async.commit_group;" ::: "memory");
    };

    auto compute = [&](int stg) {
        const uint32_t base = sb + stg * STAGE_BYTES;
#pragma unroll
        for (int kk = 0; kk < 2; ++kk) {
            const uint32_t kb = base + kk * 32;
            uint32_t ah[2][4], al[2][4];
#pragma unroll
            for (int ts = 0; ts < 2; ++ts) {
                ldsm_x4(ah[ts], kb + aRow[ts]);
                ldsm_x4(al[ts], kb + A_SPLIT_B + aRow[ts]);
            }
            // B: one ldsm_x4 per w covers n16 x k16:
            //   r4[0]=n0 k0, r4[1]=n1 k0, r4[2]=n0 k1, r4[3]=n1 k1
            uint32_t bf[3][2][2];
#pragma unroll
            for (int w = 0; w < 3; ++w) {
                uint32_t r4[4];
                ldsm_x4(r4, kb + w * 5120 + bRow);
                bf[w][0][0] = r4[0];
                bf[w][1][0] = r4[1];
                bf[w][0][1] = r4[2];
                bf[w][1][1] = r4[3];
            }
            // product-outer: 12 independent MMAs between RAW reuses
#pragma unroll
            for (int pr = 0; pr < 2; ++pr) {
#pragma unroll
                for (int w = 0; w < 3; ++w)
#pragma unroll
                    for (int ts = 0; ts < 2; ++ts)
#pragma unroll
                        for (int nt = 0; nt < 2; ++nt) {
                            const uint32_t* af = pr ? al[ts] : ah[ts];
                            mma16816(acc[w][ts][nt], af, bf[w][nt]);
                        }
            }
        }
    };

    issue_load(0, 0);
    issue_load(1, 1);
#pragma unroll 1
    for (int ic = 0; ic < NKC; ++ic) {
        if (ic < NKC - 1)
            asm volatile("cp.async.wait_group 1;" ::: "memory");
        else
            asm volatile("cp.async.wait_group 0;" ::: "memory");
        __syncthreads();
        if (ic + 2 < NKC) issue_load(ic + 2, (ic + 2) % NSTAGES);
        compute(ic % NSTAGES);
    }
    __syncthreads();   // all compute done before smem reuse by epilogue

    // ---- fused epilogue: bias + softplus + exp, then t-scan ----
    float* salpha = (float*)smem;                      // [128][66]
    float* sdrive = (float*)(smem + 33792);            // [128][66]
    float* sAp = (float*)(smem + 67584);               // [8][64]
    float* sDp = (float*)(smem + 67584 + 2048);        // [8][64]

#pragma unroll
    for (int ts = 0; ts < 2; ++ts) {
#pragma unroll
        for (int nt = 0; nt < 2; ++nt) {
            const int mloc = wm * 16 + nt * 8 + 2 * (lane & 3);
            const float2 bl = *(const float2*)&b_lam[m0 + mloc];
            const float2 bd = *(const float2*)&b_delt[m0 + mloc];
            const float2 bi = *(const float2*)&b_inp[m0 + mloc];
#pragma unroll
            for (int h = 0; h < 2; ++h) {
                const int t = wt * 32 + ts * 16 + h * 8 + (lane >> 2);
#pragma unroll
                for (int c = 0; c < 2; ++c) {
                    float zl = acc[0][ts][nt][h * 2 + c] + (c ? bl.y : bl.x);
                    float zd = acc[1][ts][nt][h * 2 + c] + (c ? bd.y : bd.x);
                    float zi = acc[2][ts][nt][h * 2 + c] + (c ? bi.y : bi.x);
                    float lamv = softplus_f(zl);
                    float dlv = softplus_f(zd);
                    salpha[t * 66 + mloc + c] = expf(-dlv * lamv);
                    sdrive[t * 66 + mloc + c] = dlv * zi;
                }
            }
        }
    }
    __syncthreads();
    {
        const int m = tid & 63;
        const int ty = tid >> 6;     // 0..7, each 16 t's
        float A = 1.f, D = 0.f;
#pragma unroll
        for (int r = 0; r < 16; ++r) {
            int t = ty * 16 + r;
            float a = salpha[t * 66 + m];
            D = a * D + sdrive[t * 66 + m];
            A *= a;
        }
        sAp[ty * 64 + m] = A;
        sDp[ty * 64 + m] = D;
    }
    __syncthreads();
    if (tid < 64) {
        float A = 1.f, D = 0.f;
#pragma unroll
        for (int r = 0; r < 8; ++r) {
            float a = sAp[r * 64 + tid];
            D = a * D + sDp[r * 64 + tid];
            A *= a;
        }
        size_t o = (size_t)tb * M_ + m0 + tid;
        g_A[o] = A;
        g_D[o] = D;
    }
}

// ---------------------------------------------------------------------------
// Kernel C: combine 16 t-tiles per (b,m), then add_pred[b] = s . W_add + b_add
// ---------------------------------------------------------------------------
__global__ void combine_kernel(const float* __restrict__ W_add,
                               const float* __restrict__ b_add,
                               float* __restrict__ out) {
    int b = blockIdx.x;
    int m = threadIdx.x;
    float s = 0.f;
#pragma unroll
    for (int tt = 0; tt < NTT2; ++tt) {
        size_t idx = ((size_t)(b * NTT2 + tt)) * M_ + m;
        s = g_A[idx] * s + g_D[idx];
    }
    float v = s * W_add[m];
    __shared__ float red[32];
    for (int off = 16; off > 0; off >>= 1)
        v += __shfl_down_sync(0xffffffffu, v, off);
    if ((m & 31) == 0) red[m >> 5] = v;
    __syncthreads();
    if (m < 32) {
        float w = red[m];
        for (int off = 16; off > 0; off >>= 1)
            w += __shfl_down_sync(0xffffffffu, w, off);
        if (m == 0) out[2 * B_ + b] = w + b_add[0];
    }
}

// ---------------------------------------------------------------------------
// Kernel P: parity path (fp64 angle accumulation)
// ---------------------------------------------------------------------------
__global__ void parity_kernel(const float* __restrict__ W_theta,
                              const float* __restrict__ b_theta,
                              const float* __restrict__ W_par,
                              const float* __restrict__ b_par,
                              float* __restrict__ out) {
    int b = blockIdx.x;
    int k = threadIdx.x;
    double acc = 0.0;
    const float* xsb = &g_xs[b * DIN_];
    for (int d = 0; d < DIN_; ++d)
        acc += (double)xsb[d] * (double)W_theta[d * K_ + k];
    acc += (double)T_ * (double)b_theta[k];
    double ang = 3.14159265358979323846 * acc;
    double sn, cs;
    sincos(ang, &sn, &cs);
    __shared__ float g[2 * K_];
    g[k] = (float)cs;
    g[K_ + k] = (float)sn;
    __syncthreads();
    if (k < 2) {
        float l = b_par[k];
        for (int j = 0; j < 2 * K_; ++j)
            l += g[j] * W_par[j * 2 + k];
        out[b * 2 + k] = l;
    }
}

// ---------------------------------------------------------------------------
extern "C" void kernel_launch(void* const* d_in, const int* in_sizes, int n_in,
                              void* d_out, int out_size) {
    const float* x       = (const float*)d_in[0];
    const float* W_theta = (const float*)d_in[1];
    const float* b_theta = (const float*)d_in[2];
    const float* W_lam   = (const float*)d_in[3];
    const float* b_lam   = (const float*)d_in[4];
    const float* W_delt  = (const float*)d_in[5];
    const float* b_delt  = (const float*)d_in[6];
    const float* W_inp   = (const float*)d_in[7];
    const float* b_inp   = (const float*)d_in[8];
    const float* W_par   = (const float*)d_in[9];
    const float* b_par   = (const float*)d_in[10];
    const float* W_add   = (const float*)d_in[11];
    const float* b_add   = (const float*)d_in[12];
    float* out = (float*)d_out;

    static int smem_set = 0;
    if (!smem_set) {
        cudaFuncSetAttribute(gssm_mma_kernel,
                             cudaFuncAttributeMaxDynamicSharedMemorySize,
                             SMEM_BYTES);
        smem_set = 1;
    }

    // Prep: split/convert inputs
    xsplit_kernel<<<((size_t)B_ * T_ * DIN_) / (256 * 8), 256>>>(x);
    wtsplit_kernel<<<dim3(32, 16, 3), 256>>>(W_lam, W_delt, W_inp);
    xs_kernel<<<dim3(DIN_ / 128, B_), 128>>>(x);

    // Main fused tensor-core GEMM + scan-reduce
    gssm_mma_kernel<<<dim3(NMB, B_ * NTT2), NTHREADS, SMEM_BYTES>>>(
        b_lam, b_delt, b_inp);

    // Heads
    parity_kernel<<<B_, K_>>>(W_theta, b_theta, W_par, b_par, out);
    combine_kernel<<<B_, M_>>>(W_add, b_add, out);
}

// round 7
// speedup vs baseline: 1.3589x; 1.0265x over previous
#include <cuda_runtime.h>
#include <cuda_fp16.h>
#include <math.h>
#include <stdint.h>

// ---------------------------------------------------------------------------
// GSSM — HMMA fp16 2-product split, round 7.
// R6 established: time ∝ HMMA count, fp32-acc HMMA rt≈16 cyc/SMSP, and the
// pipe reads 50% at saturation (suggesting a 2x-faster f16-acc variant sets
// the peak). This round: (a) lo product accumulated in f16 (zero precision
// impact; tests the rate hypothesis), (b) one sync per two k-chunks.
//
// Inputs (metadata order):
//  0: x(32,2048,512) 1: W_theta(512,64) 2: b_theta(64)
//  3: W_lam(512,1024) 4: b_lam 5: W_delt 6: b_delt 7: W_inp 8: b_inp
//  9: W_par(128,2) 10: b_par(2) 11: W_add(1024,1) 12: b_add(1)
// Output: parity_logits (32,2) at [0,64), add_pred (32,1) at [64,96)
// ---------------------------------------------------------------------------

#define B_ 32
#define T_ 2048
#define DIN_ 512
#define M_ 1024
#define K_ 64

#define TB 128               // t rows per CTA
#define MB 64                // m cols per CTA
#define KC 32                // k per sub-chunk
#define NKC (DIN_ / KC)      // 16 sub-chunks = 8 pairs
#define NPAIR 8
#define NTT2 (T_ / TB)       // 16 t-tiles per batch
#define NMB (M_ / MB)        // 16 m-tiles

#define NTHREADS 512

// smem sub-stage layout (fp16, padded rows of 40 elems = 80 B):
//   A: [2 split][128 rows][40]  = 20480 B
//   B: [3 w    ][ 64 rows][40]  = 15360 B
#define A_ROW_B 80
#define A_SPLIT_B 10240
#define STAGE_A 20480
#define STAGE_BYTES 35840
#define NSTAGES 6
#define SMEM_BYTES (STAGE_BYTES * NSTAGES)   // 215040

// ---- static device scratch (no allocation allowed) ------------------------
__device__ __half g_xhi[(size_t)B_ * T_ * DIN_];
__device__ __half g_xlo[(size_t)B_ * T_ * DIN_];
__device__ __half g_wh[3u * M_ * DIN_];    // [w][m][k] K-major, fp16
__device__ float g_A[B_ * NTT2 * M_];
__device__ float g_D[B_ * NTT2 * M_];
__device__ float g_xs[B_ * DIN_];

// ---- helpers ---------------------------------------------------------------
__device__ __forceinline__ uint32_t smem_u32(const void* p) {
    uint32_t a;
    asm("{ .reg .u64 t; cvta.to.shared.u64 t, %1; cvt.u32.u64 %0, t; }"
        : "=r"(a) : "l"(p));
    return a;
}

__device__ __forceinline__ void cp_async16(uint32_t dst, const void* src) {
    asm volatile("cp.async.cg.shared.global [%0], [%1], 16;"
                 :: "r"(dst), "l"(src) : "memory");
}

__device__ __forceinline__ void ldsm_x4(uint32_t* r, uint32_t addr) {
    asm volatile("ldmatrix.sync.aligned.m8n8.x4.shared.b16 {%0,%1,%2,%3}, [%4];"
                 : "=r"(r[0]), "=r"(r[1]), "=r"(r[2]), "=r"(r[3]) : "r"(addr));
}

__device__ __forceinline__ void mma16816(float* d, const uint32_t* a,
                                         const uint32_t* b) {
    asm volatile(
        "mma.sync.aligned.m16n8k16.row.col.f32.f16.f16.f32 "
        "{%0,%1,%2,%3}, {%4,%5,%6,%7}, {%8,%9}, {%0,%1,%2,%3};"
        : "+f"(d[0]), "+f"(d[1]), "+f"(d[2]), "+f"(d[3])
        : "r"(a[0]), "r"(a[1]), "r"(a[2]), "r"(a[3]), "r"(b[0]), "r"(b[1]));
}

// f16-accumulator variant: d/c are 2 regs of f16x2 ({c0,c1},{c2,c3})
__device__ __forceinline__ void mma16816_f16(uint32_t* d, const uint32_t* a,
                                             const uint32_t* b) {
    asm volatile(
        "mma.sync.aligned.m16n8k16.row.col.f16.f16.f16.f16 "
        "{%0,%1}, {%2,%3,%4,%5}, {%6,%7}, {%0,%1};"
        : "+r"(d[0]), "+r"(d[1])
        : "r"(a[0]), "r"(a[1]), "r"(a[2]), "r"(a[3]), "r"(b[0]), "r"(b[1]));
}

__device__ __forceinline__ float softplus_f(float z) {
    return fmaxf(z, 0.0f) + log1pf(expf(-fabsf(z)));
}

// ---------------------------------------------------------------------------
// Prep 1: split x -> fp16 hi/lo (hi+lo carries ~22 mantissa bits)
// ---------------------------------------------------------------------------
__global__ void xsplit_kernel(const float* __restrict__ x) {
    size_t i = ((size_t)blockIdx.x * 256 + threadIdx.x) * 8;
    float4 v0 = *(const float4*)(x + i);
    float4 v1 = *(const float4*)(x + i + 4);
    float f[8] = {v0.x, v0.y, v0.z, v0.w, v1.x, v1.y, v1.z, v1.w};
    __align__(16) __half h[8];
    __align__(16) __half l[8];
#pragma unroll
    for (int j = 0; j < 8; ++j) {
        h[j] = __float2half(f[j]);
        l[j] = __float2half(f[j] - __half2float(h[j]));
    }
    *(uint4*)&g_xhi[i] = *(const uint4*)h;
    *(uint4*)&g_xlo[i] = *(const uint4*)l;
}

// ---------------------------------------------------------------------------
// Prep 2: transpose W (512x1024 f32) -> [w][m][k] fp16
// ---------------------------------------------------------------------------
__global__ void wtsplit_kernel(const float* __restrict__ Wl,
                               const float* __restrict__ Wd,
                               const float* __restrict__ Wi) {
    __shared__ float tile[32][33];
    const int w = blockIdx.z;
    const float* W = (w == 0) ? Wl : ((w == 1) ? Wd : Wi);
    const int m0 = blockIdx.x * 32;
    const int k0 = blockIdx.y * 32;
    const int tx = threadIdx.x & 31;
    const int ty = threadIdx.x >> 5;
#pragma unroll
    for (int r = 0; r < 4; ++r)
        tile[ty + 8 * r][tx] = W[(size_t)(k0 + ty + 8 * r) * M_ + m0 + tx];
    __syncthreads();
#pragma unroll
    for (int r = 0; r < 4; ++r) {
        int m = ty + 8 * r;
        int k = tx;
        size_t o = ((size_t)w * M_ + m0 + m) * DIN_ + k0 + k;
        g_wh[o] = __float2half(tile[k][m]);
    }
}

// ---------------------------------------------------------------------------
// Kernel A: xs[b,d] = sum_t x[b,t,d]   (fp64 accumulation; parity branch)
// ---------------------------------------------------------------------------
__global__ void xs_kernel(const float* __restrict__ x) {
    int b = blockIdx.y;
    int d = blockIdx.x * 128 + threadIdx.x;
    const float* xp = x + (size_t)b * T_ * DIN_ + d;
    double a0 = 0.0, a1 = 0.0, a2 = 0.0, a3 = 0.0;
    for (int t = 0; t < T_; t += 4) {
        a0 += (double)xp[(size_t)(t + 0) * DIN_];
        a1 += (double)xp[(size_t)(t + 1) * DIN_];
        a2 += (double)xp[(size_t)(t + 2) * DIN_];
        a3 += (double)xp[(size_t)(t + 3) * DIN_];
    }
    g_xs[b * DIN_ + d] = (float)((a0 + a1) + (a2 + a3));
}

// ---------------------------------------------------------------------------
// Main kernel: HMMA fp16 2-product triple-GEMM + fused softplus/exp + t-scan.
// grid (16 m-tiles, 512 bt-tiles), 512 threads (16 warps: 4 t x 4 m).
// ---------------------------------------------------------------------------
__global__ void __launch_bounds__(NTHREADS, 1)
gssm_mma_kernel(const float* __restrict__ b_lam,
                const float* __restrict__ b_delt,
                const float* __restrict__ b_inp) {
    extern __shared__ __align__(128) char smem[];
    const uint32_t sb = smem_u32(smem);
    const int tid = threadIdx.x;
    const int lane = tid & 31;
    const int wid = tid >> 5;
    const int wt = wid & 3;        // t-quadrant: rows wt*32..+31
    const int wm = wid >> 2;       // m-sixteenth: cols wm*16..+15
    const int mb = blockIdx.x;
    const int tb = blockIdx.y;     // b*16 + tt
    const int m0 = mb * MB;
    const int r0 = tb * TB;

    // ---- hoisted cp.async source pointers / dest offsets -------------------
    const __half* srcA[2];
    uint32_t dstA[2];
#pragma unroll
    for (int q = 0; q < 2; ++q) {
        int idx = q * NTHREADS + tid;
        int split = idx >> 9;
        int r = (idx >> 2) & 127;
        int v = idx & 3;
        srcA[q] = (split ? g_xlo : g_xhi) + (size_t)(r0 + r) * DIN_ + v * 8;
        dstA[q] = sb + split * A_SPLIT_B + r * A_ROW_B + v * 16;
    }
    const __half* srcB[2];
    uint32_t dstB[2];
#pragma unroll
    for (int q = 0; q < 2; ++q) {
        int idx = q * NTHREADS + tid;          // q=1 valid only for tid<256
        int w = idx >> 8;                       // 0..2
        int n = (idx >> 2) & 63;
        int v = idx & 3;
        if (w > 2) w = 2;                       // clamp (unused lanes predicated)
        srcB[q] = g_wh + ((size_t)w * M_ + m0 + n) * DIN_ + v * 8;
        dstB[q] = sb + STAGE_A + w * 5120 + n * A_ROW_B + v * 16;
    }
    const bool b1_active = (tid < 256);

    // ---- hoisted ldmatrix row offsets --------------------------------------
    const int rsub = (lane & 7) + 8 * ((lane >> 3) & 1);
    const int ksub2 = 16 * (lane >> 4);           // ksub * 2 bytes
    uint32_t aRow[2];
#pragma unroll
    for (int ts = 0; ts < 2; ++ts)
        aRow[ts] = (uint32_t)((wt * 32 + ts * 16 + rsub) * A_ROW_B) + ksub2;
    const uint32_t bRow =
        (uint32_t)(STAGE_A + (wm * 16 + rsub) * A_ROW_B) + ksub2;

    float acc[3][2][2][4];      // hi product, fp32 accumulators
    uint32_t accl[3][2][2][2];  // lo product, f16x2 accumulators
#pragma unroll
    for (int w = 0; w < 3; ++w)
#pragma unroll
        for (int ts = 0; ts < 2; ++ts)
#pragma unroll
            for (int nt = 0; nt < 2; ++nt) {
#pragma unroll
                for (int f = 0; f < 4; ++f) acc[w][ts][nt][f] = 0.f;
                accl[w][ts][nt][0] = 0u;
                accl[w][ts][nt][1] = 0u;
            }

    auto issue_load = [&](int ic, int stg) {
        const uint32_t so = stg * STAGE_BYTES;
        const size_t ko = (size_t)ic * KC;
        cp_async16(dstA[0] + so, srcA[0] + ko);
        cp_async16(dstA[1] + so, srcA[1] + ko);
        cp_async16(dstB[0] + so, srcB[0] + ko);
        if (b1_active) cp_async16(dstB[1] + so, srcB[1] + ko);
    };
    auto issue_pair = [&](int p) {
        issue_load(2 * p, (2 * p) % NSTAGES);
        issue_load(2 * p + 1, (2 * p + 1) % NSTAGES);
        asm volatile("cp.async.commit_group;" ::: "memory");
    };

    auto compute = [&](int stg) {
        const uint32_t base = sb + stg * STAGE_BYTES;
#pragma unroll
        for (int kk = 0; kk < 2; ++kk) {
            const uint32_t kb = base + kk * 32;
            uint32_t ah[2][4], al[2][4];
#pragma unroll
            for (int ts = 0; ts < 2; ++ts) {
                ldsm_x4(ah[ts], kb + aRow[ts]);
                ldsm_x4(al[ts], kb + A_SPLIT_B + aRow[ts]);
            }
            uint32_t bf[3][2][2];
#pragma unroll
            for (int w = 0; w < 3; ++w) {
                uint32_t r4[4];
                ldsm_x4(r4, kb + w * 5120 + bRow);
                bf[w][0][0] = r4[0];
                bf[w][1][0] = r4[1];
                bf[w][0][1] = r4[2];
                bf[w][1][1] = r4[3];
            }
            // hi product: fp32 acc (rt~16); lo product: f16 acc (rt~8 if the
            // rate hypothesis holds)
#pragma unroll
            for (int w = 0; w < 3; ++w)
#pragma unroll
                for (int ts = 0; ts < 2; ++ts)
#pragma unroll
                    for (int nt = 0; nt < 2; ++nt)
                        mma16816(acc[w][ts][nt], ah[ts], bf[w][nt]);
#pragma unroll
            for (int w = 0; w < 3; ++w)
#pragma unroll
                for (int ts = 0; ts < 2; ++ts)
#pragma unroll
                    for (int nt = 0; nt < 2; ++nt)
                        mma16816_f16(accl[w][ts][nt], al[ts], bf[w][nt]);
        }
    };

    issue_pair(0);
    issue_pair(1);
#pragma unroll 1
    for (int p = 0; p < NPAIR; ++p) {
        if (p < NPAIR - 1)
            asm volatile("cp.async.wait_group 1;" ::: "memory");
        else
            asm volatile("cp.async.wait_group 0;" ::: "memory");
        __syncthreads();
        if (p + 2 < NPAIR) issue_pair(p + 2);
        compute((2 * p) % NSTAGES);
        compute((2 * p + 1) % NSTAGES);
    }
    __syncthreads();   // all compute done before smem reuse by epilogue

    // ---- merge lo (f16) accumulators into fp32 ----
#pragma unroll
    for (int w = 0; w < 3; ++w)
#pragma unroll
        for (int ts = 0; ts < 2; ++ts)
#pragma unroll
            for (int nt = 0; nt < 2; ++nt) {
                __half2 p0 = *reinterpret_cast<__half2*>(&accl[w][ts][nt][0]);
                __half2 p1 = *reinterpret_cast<__half2*>(&accl[w][ts][nt][1]);
                acc[w][ts][nt][0] += __low2float(p0);
                acc[w][ts][nt][1] += __high2float(p0);
                acc[w][ts][nt][2] += __low2float(p1);
                acc[w][ts][nt][3] += __high2float(p1);
            }

    // ---- fused epilogue: bias + softplus + exp, then t-scan ----
    float* salpha = (float*)smem;                      // [128][66]
    float* sdrive = (float*)(smem + 33792);            // [128][66]
    float* sAp = (float*)(smem + 67584);               // [8][64]
    float* sDp = (float*)(smem + 67584 + 2048);        // [8][64]

#pragma unroll
    for (int ts = 0; ts < 2; ++ts) {
#pragma unroll
        for (int nt = 0; nt < 2; ++nt) {
            const int mloc = wm * 16 + nt * 8 + 2 * (lane & 3);
            const float2 bl = *(const float2*)&b_lam[m0 + mloc];
            const float2 bd = *(const float2*)&b_delt[m0 + mloc];
            const float2 bi = *(const float2*)&b_inp[m0 + mloc];
#pragma unroll
            for (int h = 0; h < 2; ++h) {
                const int t = wt * 32 + ts * 16 + h * 8 + (lane >> 2);
#pragma unroll
                for (int c = 0; c < 2; ++c) {
                    float zl = acc[0][ts][nt][h * 2 + c] + (c ? bl.y : bl.x);
                    float zd = acc[1][ts][nt][h * 2 + c] + (c ? bd.y : bd.x);
                    float zi = acc[2][ts][nt][h * 2 + c] + (c ? bi.y : bi.x);
                    float lamv = softplus_f(zl);
                    float dlv = softplus_f(zd);
                    salpha[t * 66 + mloc + c] = expf(-dlv * lamv);
                    sdrive[t * 66 + mloc + c] = dlv * zi;
                }
            }
        }
    }
    __syncthreads();
    {
        const int m = tid & 63;
        const int ty = tid >> 6;     // 0..7, each 16 t's
        float A = 1.f, D = 0.f;
#pragma unroll
        for (int r = 0; r < 16; ++r) {
            int t = ty * 16 + r;
            float a = salpha[t * 66 + m];
            D = a * D + sdrive[t * 66 + m];
            A *= a;
        }
        sAp[ty * 64 + m] = A;
        sDp[ty * 64 + m] = D;
    }
    __syncthreads();
    if (tid < 64) {
        float A = 1.f, D = 0.f;
#pragma unroll
        for (int r = 0; r < 8; ++r) {
            float a = sAp[r * 64 + tid];
            D = a * D + sDp[r * 64 + tid];
            A *= a;
        }
        size_t o = (size_t)tb * M_ + m0 + tid;
        g_A[o] = A;
        g_D[o] = D;
    }
}

// ---------------------------------------------------------------------------
// Kernel C: combine 16 t-tiles per (b,m), then add_pred[b] = s . W_add + b_add
// ---------------------------------------------------------------------------
__global__ void combine_kernel(const float* __restrict__ W_add,
                               const float* __restrict__ b_add,
                               float* __restrict__ out) {
    int b = blockIdx.x;
    int m = threadIdx.x;
    float s = 0.f;
#pragma unroll
    for (int tt = 0; tt < NTT2; ++tt) {
        size_t idx = ((size_t)(b * NTT2 + tt)) * M_ + m;
        s = g_A[idx] * s + g_D[idx];
    }
    float v = s * W_add[m];
    __shared__ float red[32];
    for (int off = 16; off > 0; off >>= 1)
        v += __shfl_down_sync(0xffffffffu, v, off);
    if ((m & 31) == 0) red[m >> 5] = v;
    __syncthreads();
    if (m < 32) {
        float w = red[m];
        for (int off = 16; off > 0; off >>= 1)
            w += __shfl_down_sync(0xffffffffu, w, off);
        if (m == 0) out[2 * B_ + b] = w + b_add[0];
    }
}

// ---------------------------------------------------------------------------
// Kernel P: parity path (fp64 angle accumulation)
// ---------------------------------------------------------------------------
__global__ void parity_kernel(const float* __restrict__ W_theta,
                              const float* __restrict__ b_theta,
                              const float* __restrict__ W_par,
                              const float* __restrict__ b_par,
                              float* __restrict__ out) {
    int b = blockIdx.x;
    int k = threadIdx.x;
    double acc = 0.0;
    const float* xsb = &g_xs[b * DIN_];
    for (int d = 0; d < DIN_; ++d)
        acc += (double)xsb[d] * (double)W_theta[d * K_ + k];
    acc += (double)T_ * (double)b_theta[k];
    double ang = 3.14159265358979323846 * acc;
    double sn, cs;
    sincos(ang, &sn, &cs);
    __shared__ float g[2 * K_];
    g[k] = (float)cs;
    g[K_ + k] = (float)sn;
    __syncthreads();
    if (k < 2) {
        float l = b_par[k];
        for (int j = 0; j < 2 * K_; ++j)
            l += g[j] * W_par[j * 2 + k];
        out[b * 2 + k] = l;
    }
}

// ---------------------------------------------------------------------------
extern "C" void kernel_launch(void* const* d_in, const int* in_sizes, int n_in,
                              void* d_out, int out_size) {
    const float* x       = (const float*)d_in[0];
    const float* W_theta = (const float*)d_in[1];
    const float* b_theta = (const float*)d_in[2];
    const float* W_lam   = (const float*)d_in[3];
    const float* b_lam   = (const float*)d_in[4];
    const float* W_delt  = (const float*)d_in[5];
    const float* b_delt  = (const float*)d_in[6];
    const float* W_inp   = (const float*)d_in[7];
    const float* b_inp   = (const float*)d_in[8];
    const float* W_par   = (const float*)d_in[9];
    const float* b_par   = (const float*)d_in[10];
    const float* W_add   = (const float*)d_in[11];
    const float* b_add   = (const float*)d_in[12];
    float* out = (float*)d_out;

    static int smem_set = 0;
    if (!smem_set) {
        cudaFuncSetAttribute(gssm_mma_kernel,
                             cudaFuncAttributeMaxDynamicSharedMemorySize,
                             SMEM_BYTES);
        smem_set = 1;
    }

    // Prep: split/convert inputs
    xsplit_kernel<<<((size_t)B_ * T_ * DIN_) / (256 * 8), 256>>>(x);
    wtsplit_kernel<<<dim3(32, 16, 3), 256>>>(W_lam, W_delt, W_inp);
    xs_kernel<<<dim3(DIN_ / 128, B_), 128>>>(x);

    // Main fused tensor-core GEMM + scan-reduce
    gssm_mma_kernel<<<dim3(NMB, B_ * NTT2), NTHREADS, SMEM_BYTES>>>(
        b_lam, b_delt, b_inp);

    // Heads
    parity_kernel<<<B_, K_>>>(W_theta, b_theta, W_par, b_par, out);
    combine_kernel<<<B_, M_>>>(W_add, b_add, out);
}

// round 8
// speedup vs baseline: 2.0202x; 1.4866x over previous
#include <cuda_runtime.h>
#include <cuda_fp16.h>
#include <math.h>
#include <stdint.h>

// ---------------------------------------------------------------------------
// GSSM — HMMA single-product fp16 GEMM, round 8.
// Established (R3-R7): time ∝ mma.sync HMMA count, rt≈15cyc/SMSP regardless
// of accumulator type or scheduling. Only lever: fewer MMAs. This round drops
// the x_lo product entirely (z = fp16(x)·fp16(w), fp32 acc): half the MMAs.
// Error budget: w-rounding alone measured 1.85e-4 final; x-rounding adds an
// independent equal term -> ~3e-4 predicted vs 1e-3 threshold.
// Also: xs_kernel parallelized 8x over T (was latency-bound at ~160us).
//
// Inputs (metadata order):
//  0: x(32,2048,512) 1: W_theta(512,64) 2: b_theta(64)
//  3: W_lam(512,1024) 4: b_lam 5: W_delt 6: b_delt 7: W_inp 8: b_inp
//  9: W_par(128,2) 10: b_par(2) 11: W_add(1024,1) 12: b_add(1)
// Output: parity_logits (32,2) at [0,64), add_pred (32,1) at [64,96)
// ---------------------------------------------------------------------------

#define B_ 32
#define T_ 2048
#define DIN_ 512
#define M_ 1024
#define K_ 64

#define TB 128               // t rows per CTA
#define MB 64                // m cols per CTA
#define KC 32                // k per sub-chunk
#define NKC (DIN_ / KC)      // 16 sub-chunks = 8 pairs
#define NPAIR 8
#define NTT2 (T_ / TB)       // 16 t-tiles per batch
#define NMB (M_ / MB)        // 16 m-tiles
#define NSEG 8               // xs reduction segments

#define NTHREADS 512

// smem sub-stage layout (fp16, padded rows of 40 elems = 80 B):
//   A: [128 rows][40]  = 10240 B
//   B: [3 w][64 rows][40] = 15360 B
#define A_ROW_B 80
#define STAGE_A 10240
#define STAGE_BYTES 25600
#define NSTAGES 6
#define SMEM_BYTES (STAGE_BYTES * NSTAGES)   // 153600

// ---- static device scratch (no allocation allowed) ------------------------
__device__ __half g_xh[(size_t)B_ * T_ * DIN_];
__device__ __half g_wh[3u * M_ * DIN_];    // [w][m][k] K-major, fp16
__device__ float g_A[B_ * NTT2 * M_];
__device__ float g_D[B_ * NTT2 * M_];
__device__ double g_xsp[NSEG * B_ * DIN_]; // partial sums of x over T segments

// ---- helpers ---------------------------------------------------------------
__device__ __forceinline__ uint32_t smem_u32(const void* p) {
    uint32_t a;
    asm("{ .reg .u64 t; cvta.to.shared.u64 t, %1; cvt.u32.u64 %0, t; }"
        : "=r"(a) : "l"(p));
    return a;
}

__device__ __forceinline__ void cp_async16(uint32_t dst, const void* src) {
    asm volatile("cp.async.cg.shared.global [%0], [%1], 16;"
                 :: "r"(dst), "l"(src) : "memory");
}

__device__ __forceinline__ void ldsm_x4(uint32_t* r, uint32_t addr) {
    asm volatile("ldmatrix.sync.aligned.m8n8.x4.shared.b16 {%0,%1,%2,%3}, [%4];"
                 : "=r"(r[0]), "=r"(r[1]), "=r"(r[2]), "=r"(r[3]) : "r"(addr));
}

__device__ __forceinline__ void mma16816(float* d, const uint32_t* a,
                                         const uint32_t* b) {
    asm volatile(
        "mma.sync.aligned.m16n8k16.row.col.f32.f16.f16.f32 "
        "{%0,%1,%2,%3}, {%4,%5,%6,%7}, {%8,%9}, {%0,%1,%2,%3};"
        : "+f"(d[0]), "+f"(d[1]), "+f"(d[2]), "+f"(d[3])
        : "r"(a[0]), "r"(a[1]), "r"(a[2]), "r"(a[3]), "r"(b[0]), "r"(b[1]));
}

__device__ __forceinline__ float softplus_f(float z) {
    return fmaxf(z, 0.0f) + log1pf(expf(-fabsf(z)));
}

// ---------------------------------------------------------------------------
// Prep 1: convert x -> fp16
// ---------------------------------------------------------------------------
__global__ void xcvt_kernel(const float* __restrict__ x) {
    size_t i = ((size_t)blockIdx.x * 256 + threadIdx.x) * 8;
    float4 v0 = *(const float4*)(x + i);
    float4 v1 = *(const float4*)(x + i + 4);
    float f[8] = {v0.x, v0.y, v0.z, v0.w, v1.x, v1.y, v1.z, v1.w};
    __align__(16) __half h[8];
#pragma unroll
    for (int j = 0; j < 8; ++j) h[j] = __float2half(f[j]);
    *(uint4*)&g_xh[i] = *(const uint4*)h;
}

// ---------------------------------------------------------------------------
// Prep 2: transpose W (512x1024 f32) -> [w][m][k] fp16
// ---------------------------------------------------------------------------
__global__ void wtsplit_kernel(const float* __restrict__ Wl,
                               const float* __restrict__ Wd,
                               const float* __restrict__ Wi) {
    __shared__ float tile[32][33];
    const int w = blockIdx.z;
    const float* W = (w == 0) ? Wl : ((w == 1) ? Wd : Wi);
    const int m0 = blockIdx.x * 32;
    const int k0 = blockIdx.y * 32;
    const int tx = threadIdx.x & 31;
    const int ty = threadIdx.x >> 5;
#pragma unroll
    for (int r = 0; r < 4; ++r)
        tile[ty + 8 * r][tx] = W[(size_t)(k0 + ty + 8 * r) * M_ + m0 + tx];
    __syncthreads();
#pragma unroll
    for (int r = 0; r < 4; ++r) {
        int m = ty + 8 * r;
        int k = tx;
        size_t o = ((size_t)w * M_ + m0 + m) * DIN_ + k0 + k;
        g_wh[o] = __float2half(tile[k][m]);
    }
}

// ---------------------------------------------------------------------------
// Kernel A: partial xs over 8 T-segments (fp64 accumulation; parity branch)
// grid (4, 32, 8), 128 threads
// ---------------------------------------------------------------------------
__global__ void xs_kernel(const float* __restrict__ x) {
    int b = blockIdx.y;
    int seg = blockIdx.z;
    int d = blockIdx.x * 128 + threadIdx.x;
    const int TS = T_ / NSEG;   // 256
    const float* xp = x + ((size_t)b * T_ + (size_t)seg * TS) * DIN_ + d;
    double a0 = 0.0, a1 = 0.0, a2 = 0.0, a3 = 0.0;
    for (int t = 0; t < TS; t += 4) {
        a0 += (double)xp[(size_t)(t + 0) * DIN_];
        a1 += (double)xp[(size_t)(t + 1) * DIN_];
        a2 += (double)xp[(size_t)(t + 2) * DIN_];
        a3 += (double)xp[(size_t)(t + 3) * DIN_];
    }
    g_xsp[((size_t)seg * B_ + b) * DIN_ + d] = (a0 + a1) + (a2 + a3);
}

// ---------------------------------------------------------------------------
// Main kernel: HMMA fp16 triple-GEMM + fused softplus/exp + t-scan.
// grid (16 m-tiles, 512 bt-tiles), 512 threads (16 warps: 4 t x 4 m).
// ---------------------------------------------------------------------------
__global__ void __launch_bounds__(NTHREADS, 1)
gssm_mma_kernel(const float* __restrict__ b_lam,
                const float* __restrict__ b_delt,
                const float* __restrict__ b_inp) {
    extern __shared__ __align__(128) char smem[];
    const uint32_t sb = smem_u32(smem);
    const int tid = threadIdx.x;
    const int lane = tid & 31;
    const int wid = tid >> 5;
    const int wt = wid & 3;        // t-quadrant: rows wt*32..+31
    const int wm = wid >> 2;       // m-sixteenth: cols wm*16..+15
    const int mb = blockIdx.x;
    const int tb = blockIdx.y;     // b*16 + tt
    const int m0 = mb * MB;
    const int r0 = tb * TB;

    // ---- hoisted cp.async source pointers / dest offsets -------------------
    // A: 512 x 16B over 512 threads (1 each); B: 768 x 16B (1.5 each)
    const __half* srcA;
    uint32_t dstA;
    {
        int r = tid >> 2;
        int v = tid & 3;
        srcA = g_xh + (size_t)(r0 + r) * DIN_ + v * 8;
        dstA = sb + r * A_ROW_B + v * 16;
    }
    const __half* srcB[2];
    uint32_t dstB[2];
#pragma unroll
    for (int q = 0; q < 2; ++q) {
        int idx = q * NTHREADS + tid;          // q=1 valid only for tid<256
        int w = idx >> 8;                       // 0..2
        int n = (idx >> 2) & 63;
        int v = idx & 3;
        if (w > 2) w = 2;                       // clamp (unused lanes predicated)
        srcB[q] = g_wh + ((size_t)w * M_ + m0 + n) * DIN_ + v * 8;
        dstB[q] = sb + STAGE_A + w * 5120 + n * A_ROW_B + v * 16;
    }
    const bool b1_active = (tid < 256);

    // ---- hoisted ldmatrix row offsets --------------------------------------
    const int rsub = (lane & 7) + 8 * ((lane >> 3) & 1);
    const int ksub2 = 16 * (lane >> 4);           // ksub * 2 bytes
    uint32_t aRow[2];
#pragma unroll
    for (int ts = 0; ts < 2; ++ts)
        aRow[ts] = (uint32_t)((wt * 32 + ts * 16 + rsub) * A_ROW_B) + ksub2;
    const uint32_t bRow =
        (uint32_t)(STAGE_A + (wm * 16 + rsub) * A_ROW_B) + ksub2;

    float acc[3][2][2][4];
#pragma unroll
    for (int w = 0; w < 3; ++w)
#pragma unroll
        for (int ts = 0; ts < 2; ++ts)
#pragma unroll
            for (int nt = 0; nt < 2; ++nt)
#pragma unroll
                for (int f = 0; f < 4; ++f) acc[w][ts][nt][f] = 0.f;

    auto issue_load = [&](int ic, int stg) {
        const uint32_t so = stg * STAGE_BYTES;
        const size_t ko = (size_t)ic * KC;
        cp_async16(dstA + so, srcA + ko);
        cp_async16(dstB[0] + so, srcB[0] + ko);
        if (b1_active) cp_async16(dstB[1] + so, srcB[1] + ko);
    };
    auto issue_pair = [&](int p) {
        issue_load(2 * p, (2 * p) % NSTAGES);
        issue_load(2 * p + 1, (2 * p + 1) % NSTAGES);
        asm volatile("cp.async.commit_group;" ::: "memory");
    };

    auto compute = [&](int stg) {
        const uint32_t base = sb + stg * STAGE_BYTES;
#pragma unroll
        for (int kk = 0; kk < 2; ++kk) {
            const uint32_t kb = base + kk * 32;
            uint32_t ah[2][4];
#pragma unroll
            for (int ts = 0; ts < 2; ++ts)
                ldsm_x4(ah[ts], kb + aRow[ts]);
            uint32_t bf[3][2][2];
#pragma unroll
            for (int w = 0; w < 3; ++w) {
                uint32_t r4[4];
                ldsm_x4(r4, kb + w * 5120 + bRow);
                bf[w][0][0] = r4[0];
                bf[w][1][0] = r4[1];
                bf[w][0][1] = r4[2];
                bf[w][1][1] = r4[3];
            }
#pragma unroll
            for (int w = 0; w < 3; ++w)
#pragma unroll
                for (int ts = 0; ts < 2; ++ts)
#pragma unroll
                    for (int nt = 0; nt < 2; ++nt)
                        mma16816(acc[w][ts][nt], ah[ts], bf[w][nt]);
        }
    };

    issue_pair(0);
    issue_pair(1);
#pragma unroll 1
    for (int p = 0; p < NPAIR; ++p) {
        if (p < NPAIR - 1)
            asm volatile("cp.async.wait_group 1;" ::: "memory");
        else
            asm volatile("cp.async.wait_group 0;" ::: "memory");
        __syncthreads();
        if (p + 2 < NPAIR) issue_pair(p + 2);
        compute((2 * p) % NSTAGES);
        compute((2 * p + 1) % NSTAGES);
    }
    __syncthreads();   // all compute done before smem reuse by epilogue

    // ---- fused epilogue: bias + softplus + exp, then t-scan ----
    float* salpha = (float*)smem;                      // [128][66]
    float* sdrive = (float*)(smem + 33792);            // [128][66]
    float* sAp = (float*)(smem + 67584);               // [8][64]
    float* sDp = (float*)(smem + 67584 + 2048);        // [8][64]

#pragma unroll
    for (int ts = 0; ts < 2; ++ts) {
#pragma unroll
        for (int nt = 0; nt < 2; ++nt) {
            const int mloc = wm * 16 + nt * 8 + 2 * (lane & 3);
            const float2 bl = *(const float2*)&b_lam[m0 + mloc];
            const float2 bd = *(const float2*)&b_delt[m0 + mloc];
            const float2 bi = *(const float2*)&b_inp[m0 + mloc];
#pragma unroll
            for (int h = 0; h < 2; ++h) {
                const int t = wt * 32 + ts * 16 + h * 8 + (lane >> 2);
#pragma unroll
                for (int c = 0; c < 2; ++c) {
                    float zl = acc[0][ts][nt][h * 2 + c] + (c ? bl.y : bl.x);
                    float zd = acc[1][ts][nt][h * 2 + c] + (c ? bd.y : bd.x);
                    float zi = acc[2][ts][nt][h * 2 + c] + (c ? bi.y : bi.x);
                    float lamv = softplus_f(zl);
                    float dlv = softplus_f(zd);
                    salpha[t * 66 + mloc + c] = expf(-dlv * lamv);
                    sdrive[t * 66 + mloc + c] = dlv * zi;
                }
            }
        }
    }
    __syncthreads();
    {
        const int m = tid & 63;
        const int ty = tid >> 6;     // 0..7, each 16 t's
        float A = 1.f, D = 0.f;
#pragma unroll
        for (int r = 0; r < 16; ++r) {
            int t = ty * 16 + r;
            float a = salpha[t * 66 + m];
            D = a * D + sdrive[t * 66 + m];
            A *= a;
        }
        sAp[ty * 64 + m] = A;
        sDp[ty * 64 + m] = D;
    }
    __syncthreads();
    if (tid < 64) {
        float A = 1.f, D = 0.f;
#pragma unroll
        for (int r = 0; r < 8; ++r) {
            float a = sAp[r * 64 + tid];
            D = a * D + sDp[r * 64 + tid];
            A *= a;
        }
        size_t o = (size_t)tb * M_ + m0 + tid;
        g_A[o] = A;
        g_D[o] = D;
    }
}

// ---------------------------------------------------------------------------
// Kernel C: combine 16 t-tiles per (b,m), then add_pred[b] = s . W_add + b_add
// ---------------------------------------------------------------------------
__global__ void combine_kernel(const float* __restrict__ W_add,
                               const float* __restrict__ b_add,
                               float* __restrict__ out) {
    int b = blockIdx.x;
    int m = threadIdx.x;
    float s = 0.f;
#pragma unroll
    for (int tt = 0; tt < NTT2; ++tt) {
        size_t idx = ((size_t)(b * NTT2 + tt)) * M_ + m;
        s = g_A[idx] * s + g_D[idx];
    }
    float v = s * W_add[m];
    __shared__ float red[32];
    for (int off = 16; off > 0; off >>= 1)
        v += __shfl_down_sync(0xffffffffu, v, off);
    if ((m & 31) == 0) red[m >> 5] = v;
    __syncthreads();
    if (m < 32) {
        float w = red[m];
        for (int off = 16; off > 0; off >>= 1)
            w += __shfl_down_sync(0xffffffffu, w, off);
        if (m == 0) out[2 * B_ + b] = w + b_add[0];
    }
}

// ---------------------------------------------------------------------------
// Kernel P: parity path (fp64 angle accumulation over xs partials)
// grid 32 (per b), 64 threads (per k)
// ---------------------------------------------------------------------------
__global__ void parity_kernel(const float* __restrict__ W_theta,
                              const float* __restrict__ b_theta,
                              const float* __restrict__ W_par,
                              const float* __restrict__ b_par,
                              float* __restrict__ out) {
    int b = blockIdx.x;
    int k = threadIdx.x;
    // reduce the 8 xs partials into shared (512 doubles)
    __shared__ double xs[DIN_];
    for (int d = k; d < DIN_; d += K_) {
        double s = 0.0;
#pragma unroll
        for (int seg = 0; seg < NSEG; ++seg)
            s += g_xsp[((size_t)seg * B_ + b) * DIN_ + d];
        xs[d] = s;
    }
    __syncthreads();
    double acc = 0.0;
    for (int d = 0; d < DIN_; ++d)
        acc += xs[d] * (double)W_theta[d * K_ + k];
    acc += (double)T_ * (double)b_theta[k];
    double ang = 3.14159265358979323846 * acc;
    double sn, cs;
    sincos(ang, &sn, &cs);
    __shared__ float g[2 * K_];
    g[k] = (float)cs;
    g[K_ + k] = (float)sn;
    __syncthreads();
    if (k < 2) {
        float l = b_par[k];
        for (int j = 0; j < 2 * K_; ++j)
            l += g[j] * W_par[j * 2 + k];
        out[b * 2 + k] = l;
    }
}

// ---------------------------------------------------------------------------
extern "C" void kernel_launch(void* const* d_in, const int* in_sizes, int n_in,
                              void* d_out, int out_size) {
    const float* x       = (const float*)d_in[0];
    const float* W_theta = (const float*)d_in[1];
    const float* b_theta = (const float*)d_in[2];
    const float* W_lam   = (const float*)d_in[3];
    const float* b_lam   = (const float*)d_in[4];
    const float* W_delt  = (const float*)d_in[5];
    const float* b_delt  = (const float*)d_in[6];
    const float* W_inp   = (const float*)d_in[7];
    const float* b_inp   = (const float*)d_in[8];
    const float* W_par   = (const float*)d_in[9];
    const float* b_par   = (const float*)d_in[10];
    const float* W_add   = (const float*)d_in[11];
    const float* b_add   = (const float*)d_in[12];
    float* out = (float*)d_out;

    static int smem_set = 0;
    if (!smem_set) {
        cudaFuncSetAttribute(gssm_mma_kernel,
                             cudaFuncAttributeMaxDynamicSharedMemorySize,
                             SMEM_BYTES);
        smem_set = 1;
    }

    // Prep: convert inputs
    xcvt_kernel<<<((size_t)B_ * T_ * DIN_) / (256 * 8), 256>>>(x);
    wtsplit_kernel<<<dim3(32, 16, 3), 256>>>(W_lam, W_delt, W_inp);
    xs_kernel<<<dim3(DIN_ / 128, B_, NSEG), 128>>>(x);

    // Main fused tensor-core GEMM + scan-reduce
    gssm_mma_kernel<<<dim3(NMB, B_ * NTT2), NTHREADS, SMEM_BYTES>>>(
        b_lam, b_delt, b_inp);

    // Heads
    parity_kernel<<<B_, K_>>>(W_theta, b_theta, W_par, b_par, out);
    combine_kernel<<<B_, M_>>>(W_add, b_add, out);
}

// round 9
// speedup vs baseline: 2.0981x; 1.0385x over previous
#include <cuda_runtime.h>
#include <cuda_fp16.h>
#include <math.h>
#include <stdint.h>

// ---------------------------------------------------------------------------
// GSSM — HMMA fp16, round 9: dual-group CTAs + fused x prep.
// R8 analysis: main kernel at 76% of the 708us pure-MMA floor; the gap is
// the per-CTA epilogue/prologue bubble at occ=1 (all warps leave the tensor
// pipe to do MUFU + scan). Fix: two independent 256-thread groups per CTA,
// each with its own tile, smem ring and named barrier — one group's epilogue
// overlaps the other group's MMA mainloop. Aux fix: single fused pass over x
// (fp16 convert + fp32 segment sums; no more fp64 adds, no second read).
//
// Inputs (metadata order):
//  0: x(32,2048,512) 1: W_theta(512,64) 2: b_theta(64)
//  3: W_lam(512,1024) 4: b_lam 5: W_delt 6: b_delt 7: W_inp 8: b_inp
//  9: W_par(128,2) 10: b_par(2) 11: W_add(1024,1) 12: b_add(1)
// Output: parity_logits (32,2) at [0,64), add_pred (32,1) at [64,96)
// ---------------------------------------------------------------------------

#define B_ 32
#define T_ 2048
#define DIN_ 512
#define M_ 1024
#define K_ 64

#define TB 64                // t rows per GROUP tile
#define MB 64                // m cols per GROUP tile
#define KC 32                // k per sub-chunk
#define NKC (DIN_ / KC)      // 16 sub-chunks = 8 pairs
#define NPAIR 8
#define NTT64 (T_ / TB)      // 32 t-tiles per batch
#define NMB (M_ / MB)        // 16 m-tiles
#define NSEG 32              // xs reduction segments

#define NTHREADS 512         // 2 groups x 256

// per-group smem stage (fp16, padded rows of 40 elems = 80 B):
//   A: [64 rows][40]   = 5120 B
//   B: [3 w][64 rows][40] = 15360 B
#define A_ROW_B 80
#define STAGE_A 5120
#define STAGE_BYTES 20480
#define NSTAGES 4
#define GROUP_BYTES (STAGE_BYTES * NSTAGES)      // 81920
#define SMEM_BYTES (GROUP_BYTES * 2)             // 163840

// ---- static device scratch (no allocation allowed) ------------------------
__device__ __half g_xh[(size_t)B_ * T_ * DIN_];
__device__ __half g_wh[3u * M_ * DIN_];    // [w][m][k] K-major, fp16
__device__ float g_A[B_ * NTT64 * M_];
__device__ float g_D[B_ * NTT64 * M_];
__device__ float g_xsp[NSEG * B_ * DIN_];  // fp32 partial sums of x over T segs

// ---- helpers ---------------------------------------------------------------
__device__ __forceinline__ uint32_t smem_u32(const void* p) {
    uint32_t a;
    asm("{ .reg .u64 t; cvta.to.shared.u64 t, %1; cvt.u32.u64 %0, t; }"
        : "=r"(a) : "l"(p));
    return a;
}

__device__ __forceinline__ void cp_async16(uint32_t dst, const void* src) {
    asm volatile("cp.async.cg.shared.global [%0], [%1], 16;"
                 :: "r"(dst), "l"(src) : "memory");
}

__device__ __forceinline__ void ldsm_x4(uint32_t* r, uint32_t addr) {
    asm volatile("ldmatrix.sync.aligned.m8n8.x4.shared.b16 {%0,%1,%2,%3}, [%4];"
                 : "=r"(r[0]), "=r"(r[1]), "=r"(r[2]), "=r"(r[3]) : "r"(addr));
}

__device__ __forceinline__ void mma16816(float* d, const uint32_t* a,
                                         const uint32_t* b) {
    asm volatile(
        "mma.sync.aligned.m16n8k16.row.col.f32.f16.f16.f32 "
        "{%0,%1,%2,%3}, {%4,%5,%6,%7}, {%8,%9}, {%0,%1,%2,%3};"
        : "+f"(d[0]), "+f"(d[1]), "+f"(d[2]), "+f"(d[3])
        : "r"(a[0]), "r"(a[1]), "r"(a[2]), "r"(a[3]), "r"(b[0]), "r"(b[1]));
}

// group barrier: named barrier 1 or 2, 256 threads
__device__ __forceinline__ void barg(int g) {
    asm volatile("bar.sync %0, 256;" :: "r"(g + 1) : "memory");
}

__device__ __forceinline__ float softplus_f(float z) {
    return fmaxf(z, 0.0f) + log1pf(expf(-fabsf(z)));
}

// ---------------------------------------------------------------------------
// Prep 1 (fused): x -> fp16, and fp32 partial sums over 32 T-segments.
// grid (B_, NSEG), 128 threads; thread owns 4 consecutive d columns.
// ---------------------------------------------------------------------------
__global__ void xprep_kernel(const float* __restrict__ x) {
    const int b = blockIdx.x;
    const int seg = blockIdx.y;
    const int d0 = threadIdx.x * 4;
    const int TS = T_ / NSEG;   // 64
    const float* xp = x + ((size_t)b * T_ + (size_t)seg * TS) * DIN_ + d0;
    __half* hp = g_xh + ((size_t)b * T_ + (size_t)seg * TS) * DIN_ + d0;
    float s0 = 0.f, s1 = 0.f, s2 = 0.f, s3 = 0.f;
#pragma unroll 4
    for (int t = 0; t < TS; ++t) {
        float4 v = *(const float4*)(xp + (size_t)t * DIN_);
        s0 += v.x; s1 += v.y; s2 += v.z; s3 += v.w;
        __align__(8) __half h[4] = {__float2half(v.x), __float2half(v.y),
                                    __float2half(v.z), __float2half(v.w)};
        *(uint2*)(hp + (size_t)t * DIN_) = *(const uint2*)h;
    }
    float4 out = make_float4(s0, s1, s2, s3);
    *(float4*)&g_xsp[((size_t)seg * B_ + b) * DIN_ + d0] = out;
}

// ---------------------------------------------------------------------------
// Prep 2: transpose W (512x1024 f32) -> [w][m][k] fp16
// ---------------------------------------------------------------------------
__global__ void wtsplit_kernel(const float* __restrict__ Wl,
                               const float* __restrict__ Wd,
                               const float* __restrict__ Wi) {
    __shared__ float tile[32][33];
    const int w = blockIdx.z;
    const float* W = (w == 0) ? Wl : ((w == 1) ? Wd : Wi);
    const int m0 = blockIdx.x * 32;
    const int k0 = blockIdx.y * 32;
    const int tx = threadIdx.x & 31;
    const int ty = threadIdx.x >> 5;
#pragma unroll
    for (int r = 0; r < 4; ++r)
        tile[ty + 8 * r][tx] = W[(size_t)(k0 + ty + 8 * r) * M_ + m0 + tx];
    __syncthreads();
#pragma unroll
    for (int r = 0; r < 4; ++r) {
        int m = ty + 8 * r;
        int k = tx;
        size_t o = ((size_t)w * M_ + m0 + m) * DIN_ + k0 + k;
        g_wh[o] = __float2half(tile[k][m]);
    }
}

// ---------------------------------------------------------------------------
// Main kernel: dual-group HMMA fp16 triple-GEMM + fused epilogue + t-scan.
// grid (16 m-tiles, 512 tile-pairs), 512 threads = 2 groups x 8 warps.
// Group g handles bt-tile (blockIdx.y*2 + g): 64 t rows x 64 m cols x 3 w.
// Warp layout per group: 2(t) x 4(m); warp tile 32t x 16m x 3w.
// ---------------------------------------------------------------------------
__global__ void __launch_bounds__(NTHREADS, 1)
gssm_mma_kernel(const float* __restrict__ b_lam,
                const float* __restrict__ b_delt,
                const float* __restrict__ b_inp) {
    extern __shared__ __align__(128) char smem[];
    const int tid = threadIdx.x;
    const int g = tid >> 8;           // group 0/1
    const int gtid = tid & 255;
    const int lane = gtid & 31;
    const int gwid = gtid >> 5;       // 0..7
    const int wt = gwid & 1;          // t-half: rows wt*32..+31
    const int wm = gwid >> 1;         // m-quarter: cols wm*16..+15
    const int mb = blockIdx.x;
    const int tb = blockIdx.y * 2 + g;   // global t-tile id in [0, 1024)
    const int m0 = mb * MB;
    const int r0 = tb * TB;

    char* gsm = smem + g * GROUP_BYTES;
    const uint32_t sbg = smem_u32(gsm);

    // ---- hoisted cp.async source pointers / dest offsets -------------------
    // A: 256 x 16B over 256 threads (1 each); B: 768 x 16B (3 each)
    const __half* srcA;
    uint32_t dstA;
    {
        int r = gtid >> 2;
        int v = gtid & 3;
        srcA = g_xh + (size_t)(r0 + r) * DIN_ + v * 8;
        dstA = sbg + r * A_ROW_B + v * 16;
    }
    const __half* srcB[3];
    uint32_t dstB[3];
#pragma unroll
    for (int q = 0; q < 3; ++q) {
        int idx = q * 256 + gtid;
        int w = idx >> 8;          // exactly 0,1,2
        int n = (idx >> 2) & 63;
        int v = idx & 3;
        srcB[q] = g_wh + ((size_t)w * M_ + m0 + n) * DIN_ + v * 8;
        dstB[q] = sbg + STAGE_A + w * 5120 + n * A_ROW_B + v * 16;
    }

    // ---- hoisted ldmatrix row offsets (sbg-relative + stage added later) ---
    const int rsub = (lane & 7) + 8 * ((lane >> 3) & 1);
    const int ksub2 = 16 * (lane >> 4);
    uint32_t aRow[2];
#pragma unroll
    for (int ts = 0; ts < 2; ++ts)
        aRow[ts] = (uint32_t)((wt * 32 + ts * 16 + rsub) * A_ROW_B) + ksub2;
    const uint32_t bRow =
        (uint32_t)(STAGE_A + (wm * 16 + rsub) * A_ROW_B) + ksub2;

    float acc[3][2][2][4];
#pragma unroll
    for (int w = 0; w < 3; ++w)
#pragma unroll
        for (int ts = 0; ts < 2; ++ts)
#pragma unroll
            for (int nt = 0; nt < 2; ++nt)
#pragma unroll
                for (int f = 0; f < 4; ++f) acc[w][ts][nt][f] = 0.f;

    auto issue_load = [&](int ic) {
        const uint32_t so = (ic & 3) * STAGE_BYTES;
        const size_t ko = (size_t)ic * KC;
        cp_async16(dstA + so, srcA + ko);
        cp_async16(dstB[0] + so, srcB[0] + ko);
        cp_async16(dstB[1] + so, srcB[1] + ko);
        cp_async16(dstB[2] + so, srcB[2] + ko);
    };
    auto issue_pair = [&](int p) {
        issue_load(2 * p);
        issue_load(2 * p + 1);
        asm volatile("cp.async.commit_group;" ::: "memory");
    };

    auto compute = [&](int stg) {
        const uint32_t base = sbg + stg * STAGE_BYTES;
#pragma unroll
        for (int kk = 0; kk < 2; ++kk) {
            const uint32_t kb = base + kk * 32;
            uint32_t ah[2][4];
#pragma unroll
            for (int ts = 0; ts < 2; ++ts)
                ldsm_x4(ah[ts], kb + aRow[ts]);
            uint32_t bf[3][2][2];
#pragma unroll
            for (int w = 0; w < 3; ++w) {
                uint32_t r4[4];
                ldsm_x4(r4, kb + w * 5120 + bRow);
                bf[w][0][0] = r4[0];
                bf[w][1][0] = r4[1];
                bf[w][0][1] = r4[2];
                bf[w][1][1] = r4[3];
            }
#pragma unroll
            for (int w = 0; w < 3; ++w)
#pragma unroll
                for (int ts = 0; ts < 2; ++ts)
#pragma unroll
                    for (int nt = 0; nt < 2; ++nt)
                        mma16816(acc[w][ts][nt], ah[ts], bf[w][nt]);
        }
    };

    issue_pair(0);
    issue_pair(1);
#pragma unroll 1
    for (int p = 0; p < NPAIR; ++p) {
        if (p < NPAIR - 1)
            asm volatile("cp.async.wait_group 1;" ::: "memory");
        else
            asm volatile("cp.async.wait_group 0;" ::: "memory");
        barg(g);                          // data of pair p visible group-wide
        compute((2 * p) & 3);
        compute((2 * p + 1) & 3);
        if (p + 2 < NPAIR) {
            barg(g);                      // group done reading these stages
            issue_pair(p + 2);
        }
    }

    // ---- fused epilogue (group-local): bias + softplus + exp, t-scan ----
    // Reuses stages 0-1 of this group's region (pair 7 lived in stages 2-3,
    // so no barrier needed before the alpha/drive stores).
    float* salpha = (float*)gsm;                       // [64][66] = 16896 B
    float* sdrive = (float*)(gsm + 16896);             // [64][66]
    float* sAp = (float*)(gsm + 33792);                // [4][64]
    float* sDp = (float*)(gsm + 33792 + 1024);         // [4][64]

#pragma unroll
    for (int ts = 0; ts < 2; ++ts) {
#pragma unroll
        for (int nt = 0; nt < 2; ++nt) {
            const int mloc = wm * 16 + nt * 8 + 2 * (lane & 3);
            const float2 bl = *(const float2*)&b_lam[m0 + mloc];
            const float2 bd = *(const float2*)&b_delt[m0 + mloc];
            const float2 bi = *(const float2*)&b_inp[m0 + mloc];
#pragma unroll
            for (int h = 0; h < 2; ++h) {
                const int t = wt * 32 + ts * 16 + h * 8 + (lane >> 2);
#pragma unroll
                for (int c = 0; c < 2; ++c) {
                    float zl = acc[0][ts][nt][h * 2 + c] + (c ? bl.y : bl.x);
                    float zd = acc[1][ts][nt][h * 2 + c] + (c ? bd.y : bd.x);
                    float zi = acc[2][ts][nt][h * 2 + c] + (c ? bi.y : bi.x);
                    float lamv = softplus_f(zl);
                    float dlv = softplus_f(zd);
                    salpha[t * 66 + mloc + c] = expf(-dlv * lamv);
                    sdrive[t * 66 + mloc + c] = dlv * zi;
                }
            }
        }
    }
    barg(g);
    {
        const int m = gtid & 63;
        const int ty = gtid >> 6;    // 0..3, each 16 t's
        float A = 1.f, D = 0.f;
#pragma unroll
        for (int r = 0; r < 16; ++r) {
            int t = ty * 16 + r;
            float a = salpha[t * 66 + m];
            D = a * D + sdrive[t * 66 + m];
            A *= a;
        }
        sAp[ty * 64 + m] = A;
        sDp[ty * 64 + m] = D;
    }
    barg(g);
    if (gtid < 64) {
        float A = 1.f, D = 0.f;
#pragma unroll
        for (int r = 0; r < 4; ++r) {
            float a = sAp[r * 64 + gtid];
            D = a * D + sDp[r * 64 + gtid];
            A *= a;
        }
        size_t o = (size_t)tb * M_ + m0 + gtid;
        g_A[o] = A;
        g_D[o] = D;
    }
}

// ---------------------------------------------------------------------------
// Kernel C: combine 32 t-tiles per (b,m), then add_pred[b] = s . W_add + b_add
// ---------------------------------------------------------------------------
__global__ void combine_kernel(const float* __restrict__ W_add,
                               const float* __restrict__ b_add,
                               float* __restrict__ out) {
    int b = blockIdx.x;
    int m = threadIdx.x;
    float s = 0.f;
#pragma unroll
    for (int tt = 0; tt < NTT64; ++tt) {
        size_t idx = ((size_t)(b * NTT64 + tt)) * M_ + m;
        s = g_A[idx] * s + g_D[idx];
    }
    float v = s * W_add[m];
    __shared__ float red[32];
    for (int off = 16; off > 0; off >>= 1)
        v += __shfl_down_sync(0xffffffffu, v, off);
    if ((m & 31) == 0) red[m >> 5] = v;
    __syncthreads();
    if (m < 32) {
        float w = red[m];
        for (int off = 16; off > 0; off >>= 1)
            w += __shfl_down_sync(0xffffffffu, w, off);
        if (m == 0) out[2 * B_ + b] = w + b_add[0];
    }
}

// ---------------------------------------------------------------------------
// Kernel P: parity path. Reduce 32 fp32 partials per (b,d) in fp64, then
// fp64 dot with W_theta, sincos, small head.
// ---------------------------------------------------------------------------
__global__ void parity_kernel(const float* __restrict__ W_theta,
                              const float* __restrict__ b_theta,
                              const float* __restrict__ W_par,
                              const float* __restrict__ b_par,
                              float* __restrict__ out) {
    int b = blockIdx.x;
    int k = threadIdx.x;
    __shared__ double xs[DIN_];
    for (int d = k; d < DIN_; d += K_) {
        double s = 0.0;
#pragma unroll
        for (int seg = 0; seg < NSEG; ++seg)
            s += (double)g_xsp[((size_t)seg * B_ + b) * DIN_ + d];
        xs[d] = s;
    }
    __syncthreads();
    double acc = 0.0;
    for (int d = 0; d < DIN_; ++d)
        acc += xs[d] * (double)W_theta[d * K_ + k];
    acc += (double)T_ * (double)b_theta[k];
    double ang = 3.14159265358979323846 * acc;
    double sn, cs;
    sincos(ang, &sn, &cs);
    __shared__ float gf[2 * K_];
    gf[k] = (float)cs;
    gf[K_ + k] = (float)sn;
    __syncthreads();
    if (k < 2) {
        float l = b_par[k];
        for (int j = 0; j < 2 * K_; ++j)
            l += gf[j] * W_par[j * 2 + k];
        out[b * 2 + k] = l;
    }
}

// ---------------------------------------------------------------------------
extern "C" void kernel_launch(void* const* d_in, const int* in_sizes, int n_in,
                              void* d_out, int out_size) {
    const float* x       = (const float*)d_in[0];
    const float* W_theta = (const float*)d_in[1];
    const float* b_theta = (const float*)d_in[2];
    const float* W_lam   = (const float*)d_in[3];
    const float* b_lam   = (const float*)d_in[4];
    const float* W_delt  = (const float*)d_in[5];
    const float* b_delt  = (const float*)d_in[6];
    const float* W_inp   = (const float*)d_in[7];
    const float* b_inp   = (const float*)d_in[8];
    const float* W_par   = (const float*)d_in[9];
    const float* b_par   = (const float*)d_in[10];
    const float* W_add   = (const float*)d_in[11];
    const float* b_add   = (const float*)d_in[12];
    float* out = (float*)d_out;

    static int smem_set = 0;
    if (!smem_set) {
        cudaFuncSetAttribute(gssm_mma_kernel,
                             cudaFuncAttributeMaxDynamicSharedMemorySize,
                             SMEM_BYTES);
        smem_set = 1;
    }

    // Prep: fused x convert + partial sums; W transpose
    xprep_kernel<<<dim3(B_, NSEG), 128>>>(x);
    wtsplit_kernel<<<dim3(32, 16, 3), 256>>>(W_lam, W_delt, W_inp);

    // Main fused tensor-core GEMM + scan-reduce (dual-group CTAs)
    gssm_mma_kernel<<<dim3(NMB, (B_ * NTT64) / 2), NTHREADS, SMEM_BYTES>>>(
        b_lam, b_delt, b_inp);

    // Heads
    parity_kernel<<<B_, K_>>>(W_theta, b_theta, W_par, b_par, out);
    combine_kernel<<<B_, M_>>>(W_add, b_add, out);
}

// round 10
// speedup vs baseline: 2.3164x; 1.1041x over previous
#include <cuda_runtime.h>
#include <cuda_fp16.h>
#include <math.h>
#include <stdint.h>

// ---------------------------------------------------------------------------
// GSSM — HMMA fp16, round 10.
// R9 decomposition: dual-group main kernel REGRESSED (~985 vs R8's 933us);
// the round's win came from the fused x-prep. So: revert main to the R8
// structure verbatim, keep fused xprep, and fix the newly-exposed parity
// kernel (75.9us, occ 3.1%: serial fp64 dot) with an 8-way split + shfl.
//
// Inputs (metadata order):
//  0: x(32,2048,512) 1: W_theta(512,64) 2: b_theta(64)
//  3: W_lam(512,1024) 4: b_lam 5: W_delt 6: b_delt 7: W_inp 8: b_inp
//  9: W_par(128,2) 10: b_par(2) 11: W_add(1024,1) 12: b_add(1)
// Output: parity_logits (32,2) at [0,64), add_pred (32,1) at [64,96)
// ---------------------------------------------------------------------------

#define B_ 32
#define T_ 2048
#define DIN_ 512
#define M_ 1024
#define K_ 64

#define TB 128               // t rows per CTA
#define MB 64                // m cols per CTA
#define KC 32                // k per sub-chunk
#define NKC (DIN_ / KC)      // 16 sub-chunks = 8 pairs
#define NPAIR 8
#define NTT2 (T_ / TB)       // 16 t-tiles per batch
#define NMB (M_ / MB)        // 16 m-tiles
#define NSEG 32              // xs reduction segments

#define NTHREADS 512

// smem sub-stage layout (fp16, padded rows of 40 elems = 80 B):
//   A: [128 rows][40]  = 10240 B
//   B: [3 w][64 rows][40] = 15360 B
#define A_ROW_B 80
#define STAGE_A 10240
#define STAGE_BYTES 25600
#define NSTAGES 6
#define SMEM_BYTES (STAGE_BYTES * NSTAGES)   // 153600

// ---- static device scratch (no allocation allowed) ------------------------
__device__ __half g_xh[(size_t)B_ * T_ * DIN_];
__device__ __half g_wh[3u * M_ * DIN_];    // [w][m][k] K-major, fp16
__device__ float g_A[B_ * NTT2 * M_];
__device__ float g_D[B_ * NTT2 * M_];
__device__ float g_xsp[NSEG * B_ * DIN_];  // fp32 partial sums of x over T segs

// ---- helpers ---------------------------------------------------------------
__device__ __forceinline__ uint32_t smem_u32(const void* p) {
    uint32_t a;
    asm("{ .reg .u64 t; cvta.to.shared.u64 t, %1; cvt.u32.u64 %0, t; }"
        : "=r"(a) : "l"(p));
    return a;
}

__device__ __forceinline__ void cp_async16(uint32_t dst, const void* src) {
    asm volatile("cp.async.cg.shared.global [%0], [%1], 16;"
                 :: "r"(dst), "l"(src) : "memory");
}

__device__ __forceinline__ void ldsm_x4(uint32_t* r, uint32_t addr) {
    asm volatile("ldmatrix.sync.aligned.m8n8.x4.shared.b16 {%0,%1,%2,%3}, [%4];"
                 : "=r"(r[0]), "=r"(r[1]), "=r"(r[2]), "=r"(r[3]) : "r"(addr));
}

__device__ __forceinline__ void mma16816(float* d, const uint32_t* a,
                                         const uint32_t* b) {
    asm volatile(
        "mma.sync.aligned.m16n8k16.row.col.f32.f16.f16.f32 "
        "{%0,%1,%2,%3}, {%4,%5,%6,%7}, {%8,%9}, {%0,%1,%2,%3};"
        : "+f"(d[0]), "+f"(d[1]), "+f"(d[2]), "+f"(d[3])
        : "r"(a[0]), "r"(a[1]), "r"(a[2]), "r"(a[3]), "r"(b[0]), "r"(b[1]));
}

__device__ __forceinline__ float softplus_f(float z) {
    return fmaxf(z, 0.0f) + log1pf(expf(-fabsf(z)));
}

// ---------------------------------------------------------------------------
// Prep 1 (fused): x -> fp16, and fp32 partial sums over 32 T-segments.
// grid (B_, NSEG), 128 threads; thread owns 4 consecutive d columns.
// ---------------------------------------------------------------------------
__global__ void xprep_kernel(const float* __restrict__ x) {
    const int b = blockIdx.x;
    const int seg = blockIdx.y;
    const int d0 = threadIdx.x * 4;
    const int TS = T_ / NSEG;   // 64
    const float* xp = x + ((size_t)b * T_ + (size_t)seg * TS) * DIN_ + d0;
    __half* hp = g_xh + ((size_t)b * T_ + (size_t)seg * TS) * DIN_ + d0;
    float s0 = 0.f, s1 = 0.f, s2 = 0.f, s3 = 0.f;
#pragma unroll 4
    for (int t = 0; t < TS; ++t) {
        float4 v = *(const float4*)(xp + (size_t)t * DIN_);
        s0 += v.x; s1 += v.y; s2 += v.z; s3 += v.w;
        __align__(8) __half h[4] = {__float2half(v.x), __float2half(v.y),
                                    __float2half(v.z), __float2half(v.w)};
        *(uint2*)(hp + (size_t)t * DIN_) = *(const uint2*)h;
    }
    float4 out = make_float4(s0, s1, s2, s3);
    *(float4*)&g_xsp[((size_t)seg * B_ + b) * DIN_ + d0] = out;
}

// ---------------------------------------------------------------------------
// Prep 2: transpose W (512x1024 f32) -> [w][m][k] fp16
// ---------------------------------------------------------------------------
__global__ void wtsplit_kernel(const float* __restrict__ Wl,
                               const float* __restrict__ Wd,
                               const float* __restrict__ Wi) {
    __shared__ float tile[32][33];
    const int w = blockIdx.z;
    const float* W = (w == 0) ? Wl : ((w == 1) ? Wd : Wi);
    const int m0 = blockIdx.x * 32;
    const int k0 = blockIdx.y * 32;
    const int tx = threadIdx.x & 31;
    const int ty = threadIdx.x >> 5;
#pragma unroll
    for (int r = 0; r < 4; ++r)
        tile[ty + 8 * r][tx] = W[(size_t)(k0 + ty + 8 * r) * M_ + m0 + tx];
    __syncthreads();
#pragma unroll
    for (int r = 0; r < 4; ++r) {
        int m = ty + 8 * r;
        int k = tx;
        size_t o = ((size_t)w * M_ + m0 + m) * DIN_ + k0 + k;
        g_wh[o] = __float2half(tile[k][m]);
    }
}

// ---------------------------------------------------------------------------
// Main kernel (R8 structure): HMMA fp16 triple-GEMM + fused epilogue + scan.
// grid (16 m-tiles, 512 bt-tiles), 512 threads (16 warps: 4 t x 4 m).
// ---------------------------------------------------------------------------
__global__ void __launch_bounds__(NTHREADS, 1)
gssm_mma_kernel(const float* __restrict__ b_lam,
                const float* __restrict__ b_delt,
                const float* __restrict__ b_inp) {
    extern __shared__ __align__(128) char smem[];
    const uint32_t sb = smem_u32(smem);
    const int tid = threadIdx.x;
    const int lane = tid & 31;
    const int wid = tid >> 5;
    const int wt = wid & 3;        // t-quadrant: rows wt*32..+31
    const int wm = wid >> 2;       // m-sixteenth: cols wm*16..+15
    const int mb = blockIdx.x;
    const int tb = blockIdx.y;     // b*16 + tt
    const int m0 = mb * MB;
    const int r0 = tb * TB;

    // ---- hoisted cp.async source pointers / dest offsets -------------------
    const __half* srcA;
    uint32_t dstA;
    {
        int r = tid >> 2;
        int v = tid & 3;
        srcA = g_xh + (size_t)(r0 + r) * DIN_ + v * 8;
        dstA = sb + r * A_ROW_B + v * 16;
    }
    const __half* srcB[2];
    uint32_t dstB[2];
#pragma unroll
    for (int q = 0; q < 2; ++q) {
        int idx = q * NTHREADS + tid;          // q=1 valid only for tid<256
        int w = idx >> 8;                       // 0..2
        int n = (idx >> 2) & 63;
        int v = idx & 3;
        if (w > 2) w = 2;                       // clamp (unused lanes predicated)
        srcB[q] = g_wh + ((size_t)w * M_ + m0 + n) * DIN_ + v * 8;
        dstB[q] = sb + STAGE_A + w * 5120 + n * A_ROW_B + v * 16;
    }
    const bool b1_active = (tid < 256);

    // ---- hoisted ldmatrix row offsets --------------------------------------
    const int rsub = (lane & 7) + 8 * ((lane >> 3) & 1);
    const int ksub2 = 16 * (lane >> 4);           // ksub * 2 bytes
    uint32_t aRow[2];
#pragma unroll
    for (int ts = 0; ts < 2; ++ts)
        aRow[ts] = (uint32_t)((wt * 32 + ts * 16 + rsub) * A_ROW_B) + ksub2;
    const uint32_t bRow =
        (uint32_t)(STAGE_A + (wm * 16 + rsub) * A_ROW_B) + ksub2;

    float acc[3][2][2][4];
#pragma unroll
    for (int w = 0; w < 3; ++w)
#pragma unroll
        for (int ts = 0; ts < 2; ++ts)
#pragma unroll
            for (int nt = 0; nt < 2; ++nt)
#pragma unroll
                for (int f = 0; f < 4; ++f) acc[w][ts][nt][f] = 0.f;

    auto issue_load = [&](int ic, int stg) {
        const uint32_t so = stg * STAGE_BYTES;
        const size_t ko = (size_t)ic * KC;
        cp_async16(dstA + so, srcA + ko);
        cp_async16(dstB[0] + so, srcB[0] + ko);
        if (b1_active) cp_async16(dstB[1] + so, srcB[1] + ko);
    };
    auto issue_pair = [&](int p) {
        issue_load(2 * p, (2 * p) % NSTAGES);
        issue_load(2 * p + 1, (2 * p + 1) % NSTAGES);
        asm volatile("cp.async.commit_group;" ::: "memory");
    };

    auto compute = [&](int stg) {
        const uint32_t base = sb + stg * STAGE_BYTES;
#pragma unroll
        for (int kk = 0; kk < 2; ++kk) {
            const uint32_t kb = base + kk * 32;
            uint32_t ah[2][4];
#pragma unroll
            for (int ts = 0; ts < 2; ++ts)
                ldsm_x4(ah[ts], kb + aRow[ts]);
            uint32_t bf[3][2][2];
#pragma unroll
            for (int w = 0; w < 3; ++w) {
                uint32_t r4[4];
                ldsm_x4(r4, kb + w * 5120 + bRow);
                bf[w][0][0] = r4[0];
                bf[w][1][0] = r4[1];
                bf[w][0][1] = r4[2];
                bf[w][1][1] = r4[3];
            }
#pragma unroll
            for (int w = 0; w < 3; ++w)
#pragma unroll
                for (int ts = 0; ts < 2; ++ts)
#pragma unroll
                    for (int nt = 0; nt < 2; ++nt)
                        mma16816(acc[w][ts][nt], ah[ts], bf[w][nt]);
        }
    };

    issue_pair(0);
    issue_pair(1);
#pragma unroll 1
    for (int p = 0; p < NPAIR; ++p) {
        if (p < NPAIR - 1)
            asm volatile("cp.async.wait_group 1;" ::: "memory");
        else
            asm volatile("cp.async.wait_group 0;" ::: "memory");
        __syncthreads();
        if (p + 2 < NPAIR) issue_pair(p + 2);
        compute((2 * p) % NSTAGES);
        compute((2 * p + 1) % NSTAGES);
    }
    __syncthreads();   // all compute done before smem reuse by epilogue

    // ---- fused epilogue: bias + softplus + exp, then t-scan ----
    float* salpha = (float*)smem;                      // [128][66]
    float* sdrive = (float*)(smem + 33792);            // [128][66]
    float* sAp = (float*)(smem + 67584);               // [8][64]
    float* sDp = (float*)(smem + 67584 + 2048);        // [8][64]

#pragma unroll
    for (int ts = 0; ts < 2; ++ts) {
#pragma unroll
        for (int nt = 0; nt < 2; ++nt) {
            const int mloc = wm * 16 + nt * 8 + 2 * (lane & 3);
            const float2 bl = *(const float2*)&b_lam[m0 + mloc];
            const float2 bd = *(const float2*)&b_delt[m0 + mloc];
            const float2 bi = *(const float2*)&b_inp[m0 + mloc];
#pragma unroll
            for (int h = 0; h < 2; ++h) {
                const int t = wt * 32 + ts * 16 + h * 8 + (lane >> 2);
#pragma unroll
                for (int c = 0; c < 2; ++c) {
                    float zl = acc[0][ts][nt][h * 2 + c] + (c ? bl.y : bl.x);
                    float zd = acc[1][ts][nt][h * 2 + c] + (c ? bd.y : bd.x);
                    float zi = acc[2][ts][nt][h * 2 + c] + (c ? bi.y : bi.x);
                    float lamv = softplus_f(zl);
                    float dlv = softplus_f(zd);
                    salpha[t * 66 + mloc + c] = expf(-dlv * lamv);
                    sdrive[t * 66 + mloc + c] = dlv * zi;
                }
            }
        }
    }
    __syncthreads();
    {
        const int m = tid & 63;
        const int ty = tid >> 6;     // 0..7, each 16 t's
        float A = 1.f, D = 0.f;
#pragma unroll
        for (int r = 0; r < 16; ++r) {
            int t = ty * 16 + r;
            float a = salpha[t * 66 + m];
            D = a * D + sdrive[t * 66 + m];
            A *= a;
        }
        sAp[ty * 64 + m] = A;
        sDp[ty * 64 + m] = D;
    }
    __syncthreads();
    if (tid < 64) {
        float A = 1.f, D = 0.f;
#pragma unroll
        for (int r = 0; r < 8; ++r) {
            float a = sAp[r * 64 + tid];
            D = a * D + sDp[r * 64 + tid];
            A *= a;
        }
        size_t o = (size_t)tb * M_ + m0 + tid;
        g_A[o] = A;
        g_D[o] = D;
    }
}

// ---------------------------------------------------------------------------
// Kernel C: combine 16 t-tiles per (b,m), then add_pred[b] = s . W_add + b_add
// ---------------------------------------------------------------------------
__global__ void combine_kernel(const float* __restrict__ W_add,
                               const float* __restrict__ b_add,
                               float* __restrict__ out) {
    int b = blockIdx.x;
    int m = threadIdx.x;
    float s = 0.f;
#pragma unroll
    for (int tt = 0; tt < NTT2; ++tt) {
        size_t idx = ((size_t)(b * NTT2 + tt)) * M_ + m;
        s = g_A[idx] * s + g_D[idx];
    }
    float v = s * W_add[m];
    __shared__ float red[32];
    for (int off = 16; off > 0; off >>= 1)
        v += __shfl_down_sync(0xffffffffu, v, off);
    if ((m & 31) == 0) red[m >> 5] = v;
    __syncthreads();
    if (m < 32) {
        float w = red[m];
        for (int off = 16; off > 0; off >>= 1)
            w += __shfl_down_sync(0xffffffffu, w, off);
        if (m == 0) out[2 * B_ + b] = w + b_add[0];
    }
}

// ---------------------------------------------------------------------------
// Kernel P: parity path, parallelized. 512 threads per b.
// Phase 1: xs[d] = sum of 32 fp32 partials (fp64), d = tid.
// Phase 2: thread (k, q) = (tid>>3, tid&7) accumulates 64 d's in fp64 with
//          2-way ILP, then shfl-reduce over the 8 q's; q==0 does sincos.
// ---------------------------------------------------------------------------
__global__ void parity_kernel(const float* __restrict__ W_theta,
                              const float* __restrict__ b_theta,
                              const float* __restrict__ W_par,
                              const float* __restrict__ b_par,
                              float* __restrict__ out) {
    int b = blockIdx.x;
    int tid = threadIdx.x;
    __shared__ double xs[DIN_];
    {
        double s = 0.0;
#pragma unroll
        for (int seg = 0; seg < NSEG; ++seg)
            s += (double)g_xsp[((size_t)seg * B_ + b) * DIN_ + tid];
        xs[tid] = s;
    }
    __syncthreads();
    const int k = tid >> 3;
    const int q = tid & 7;
    double a0 = 0.0, a1 = 0.0;
    const int dbase = q * 64;
#pragma unroll 8
    for (int i = 0; i < 64; i += 2) {
        a0 += xs[dbase + i] * (double)W_theta[(dbase + i) * K_ + k];
        a1 += xs[dbase + i + 1] * (double)W_theta[(dbase + i + 1) * K_ + k];
    }
    double acc = a0 + a1;
#pragma unroll
    for (int off = 4; off > 0; off >>= 1)
        acc += __shfl_down_sync(0xffffffffu, acc, off);
    __shared__ float gf[2 * K_];
    if (q == 0) {
        acc += (double)T_ * (double)b_theta[k];
        double ang = 3.14159265358979323846 * acc;
        double sn, cs;
        sincos(ang, &sn, &cs);
        gf[k] = (float)cs;
        gf[K_ + k] = (float)sn;
    }
    __syncthreads();
    if (tid < 2) {
        float l = b_par[tid];
        for (int j = 0; j < 2 * K_; ++j)
            l += gf[j] * W_par[j * 2 + tid];
        out[b * 2 + tid] = l;
    }
}

// ---------------------------------------------------------------------------
extern "C" void kernel_launch(void* const* d_in, const int* in_sizes, int n_in,
                              void* d_out, int out_size) {
    const float* x       = (const float*)d_in[0];
    const float* W_theta = (const float*)d_in[1];
    const float* b_theta = (const float*)d_in[2];
    const float* W_lam   = (const float*)d_in[3];
    const float* b_lam   = (const float*)d_in[4];
    const float* W_delt  = (const float*)d_in[5];
    const float* b_delt  = (const float*)d_in[6];
    const float* W_inp   = (const float*)d_in[7];
    const float* b_inp   = (const float*)d_in[8];
    const float* W_par   = (const float*)d_in[9];
    const float* b_par   = (const float*)d_in[10];
    const float* W_add   = (const float*)d_in[11];
    const float* b_add   = (const float*)d_in[12];
    float* out = (float*)d_out;

    static int smem_set = 0;
    if (!smem_set) {
        cudaFuncSetAttribute(gssm_mma_kernel,
                             cudaFuncAttributeMaxDynamicSharedMemorySize,
                             SMEM_BYTES);
        smem_set = 1;
    }

    // Prep: fused x convert + partial sums; W transpose
    xprep_kernel<<<dim3(B_, NSEG), 128>>>(x);
    wtsplit_kernel<<<dim3(32, 16, 3), 256>>>(W_lam, W_delt, W_inp);

    // Main fused tensor-core GEMM + scan-reduce (R8 structure)
    gssm_mma_kernel<<<dim3(NMB, B_ * NTT2), NTHREADS, SMEM_BYTES>>>(
        b_lam, b_delt, b_inp);

    // Heads
    parity_kernel<<<B_, DIN_>>>(W_theta, b_theta, W_par, b_par, out);
    combine_kernel<<<B_, M_>>>(W_add, b_add, out);
}

// round 11
// speedup vs baseline: 2.5095x; 1.0834x over previous
#include <cuda_runtime.h>
#include <cuda_fp16.h>
#include <math.h>
#include <stdint.h>

// ---------------------------------------------------------------------------
// GSSM — HMMA fp16, round 11.
// R10 residue analysis: main-kernel overhead (~3.3us/wave) matches the issue
// cost of the PRECISE expf/log1pf software paths in the epilogue (tensor pipe
// idles while all warps grind ALU polynomials). Swap to MUFU fast intrinsics
// (__expf/__logf): ~6x fewer instructions, error ~5e-7/op — invisible next
// to the established 2.57e-4. Also: parity kernel remapped for coalesced
// W_theta loads (was 32 lines/instr, now 1).
//
// Inputs (metadata order):
//  0: x(32,2048,512) 1: W_theta(512,64) 2: b_theta(64)
//  3: W_lam(512,1024) 4: b_lam 5: W_delt 6: b_delt 7: W_inp 8: b_inp
//  9: W_par(128,2) 10: b_par(2) 11: W_add(1024,1) 12: b_add(1)
// Output: parity_logits (32,2) at [0,64), add_pred (32,1) at [64,96)
// ---------------------------------------------------------------------------

#define B_ 32
#define T_ 2048
#define DIN_ 512
#define M_ 1024
#define K_ 64

#define TB 128               // t rows per CTA
#define MB 64                // m cols per CTA
#define KC 32                // k per sub-chunk
#define NKC (DIN_ / KC)      // 16 sub-chunks = 8 pairs
#define NPAIR 8
#define NTT2 (T_ / TB)       // 16 t-tiles per batch
#define NMB (M_ / MB)        // 16 m-tiles
#define NSEG 32              // xs reduction segments

#define NTHREADS 512

// smem sub-stage layout (fp16, padded rows of 40 elems = 80 B):
//   A: [128 rows][40]  = 10240 B
//   B: [3 w][64 rows][40] = 15360 B
#define A_ROW_B 80
#define STAGE_A 10240
#define STAGE_BYTES 25600
#define NSTAGES 6
#define SMEM_BYTES (STAGE_BYTES * NSTAGES)   // 153600

// ---- static device scratch (no allocation allowed) ------------------------
__device__ __half g_xh[(size_t)B_ * T_ * DIN_];
__device__ __half g_wh[3u * M_ * DIN_];    // [w][m][k] K-major, fp16
__device__ float g_A[B_ * NTT2 * M_];
__device__ float g_D[B_ * NTT2 * M_];
__device__ float g_xsp[NSEG * B_ * DIN_];  // fp32 partial sums of x over T segs

// ---- helpers ---------------------------------------------------------------
__device__ __forceinline__ uint32_t smem_u32(const void* p) {
    uint32_t a;
    asm("{ .reg .u64 t; cvta.to.shared.u64 t, %1; cvt.u32.u64 %0, t; }"
        : "=r"(a) : "l"(p));
    return a;
}

__device__ __forceinline__ void cp_async16(uint32_t dst, const void* src) {
    asm volatile("cp.async.cg.shared.global [%0], [%1], 16;"
                 :: "r"(dst), "l"(src) : "memory");
}

__device__ __forceinline__ void ldsm_x4(uint32_t* r, uint32_t addr) {
    asm volatile("ldmatrix.sync.aligned.m8n8.x4.shared.b16 {%0,%1,%2,%3}, [%4];"
                 : "=r"(r[0]), "=r"(r[1]), "=r"(r[2]), "=r"(r[3]) : "r"(addr));
}

__device__ __forceinline__ void mma16816(float* d, const uint32_t* a,
                                         const uint32_t* b) {
    asm volatile(
        "mma.sync.aligned.m16n8k16.row.col.f32.f16.f16.f32 "
        "{%0,%1,%2,%3}, {%4,%5,%6,%7}, {%8,%9}, {%0,%1,%2,%3};"
        : "+f"(d[0]), "+f"(d[1]), "+f"(d[2]), "+f"(d[3])
        : "r"(a[0]), "r"(a[1]), "r"(a[2]), "r"(a[3]), "r"(b[0]), "r"(b[1]));
}

// fast softplus: MUFU ex2/lg2 path; abs err < ~1e-6 over the active range
__device__ __forceinline__ float softplus_fast(float z) {
    float e = __expf(-fabsf(z));
    return fmaxf(z, 0.0f) + __logf(1.0f + e);
}

// ---------------------------------------------------------------------------
// Prep 1 (fused): x -> fp16, and fp32 partial sums over 32 T-segments.
// grid (B_, NSEG), 128 threads; thread owns 4 consecutive d columns.
// ---------------------------------------------------------------------------
__global__ void xprep_kernel(const float* __restrict__ x) {
    const int b = blockIdx.x;
    const int seg = blockIdx.y;
    const int d0 = threadIdx.x * 4;
    const int TS = T_ / NSEG;   // 64
    const float* xp = x + ((size_t)b * T_ + (size_t)seg * TS) * DIN_ + d0;
    __half* hp = g_xh + ((size_t)b * T_ + (size_t)seg * TS) * DIN_ + d0;
    float s0 = 0.f, s1 = 0.f, s2 = 0.f, s3 = 0.f;
#pragma unroll 4
    for (int t = 0; t < TS; ++t) {
        float4 v = *(const float4*)(xp + (size_t)t * DIN_);
        s0 += v.x; s1 += v.y; s2 += v.z; s3 += v.w;
        __align__(8) __half h[4] = {__float2half(v.x), __float2half(v.y),
                                    __float2half(v.z), __float2half(v.w)};
        *(uint2*)(hp + (size_t)t * DIN_) = *(const uint2*)h;
    }
    float4 out = make_float4(s0, s1, s2, s3);
    *(float4*)&g_xsp[((size_t)seg * B_ + b) * DIN_ + d0] = out;
}

// ---------------------------------------------------------------------------
// Prep 2: transpose W (512x1024 f32) -> [w][m][k] fp16
// ---------------------------------------------------------------------------
__global__ void wtsplit_kernel(const float* __restrict__ Wl,
                               const float* __restrict__ Wd,
                               const float* __restrict__ Wi) {
    __shared__ float tile[32][33];
    const int w = blockIdx.z;
    const float* W = (w == 0) ? Wl : ((w == 1) ? Wd : Wi);
    const int m0 = blockIdx.x * 32;
    const int k0 = blockIdx.y * 32;
    const int tx = threadIdx.x & 31;
    const int ty = threadIdx.x >> 5;
#pragma unroll
    for (int r = 0; r < 4; ++r)
        tile[ty + 8 * r][tx] = W[(size_t)(k0 + ty + 8 * r) * M_ + m0 + tx];
    __syncthreads();
#pragma unroll
    for (int r = 0; r < 4; ++r) {
        int m = ty + 8 * r;
        int k = tx;
        size_t o = ((size_t)w * M_ + m0 + m) * DIN_ + k0 + k;
        g_wh[o] = __float2half(tile[k][m]);
    }
}

// ---------------------------------------------------------------------------
// Main kernel (R8 structure): HMMA fp16 triple-GEMM + fused epilogue + scan.
// grid (16 m-tiles, 512 bt-tiles), 512 threads (16 warps: 4 t x 4 m).
// ---------------------------------------------------------------------------
__global__ void __launch_bounds__(NTHREADS, 1)
gssm_mma_kernel(const float* __restrict__ b_lam,
                const float* __restrict__ b_delt,
                const float* __restrict__ b_inp) {
    extern __shared__ __align__(128) char smem[];
    const uint32_t sb = smem_u32(smem);
    const int tid = threadIdx.x;
    const int lane = tid & 31;
    const int wid = tid >> 5;
    const int wt = wid & 3;        // t-quadrant: rows wt*32..+31
    const int wm = wid >> 2;       // m-sixteenth: cols wm*16..+15
    const int mb = blockIdx.x;
    const int tb = blockIdx.y;     // b*16 + tt
    const int m0 = mb * MB;
    const int r0 = tb * TB;

    // ---- hoisted cp.async source pointers / dest offsets -------------------
    const __half* srcA;
    uint32_t dstA;
    {
        int r = tid >> 2;
        int v = tid & 3;
        srcA = g_xh + (size_t)(r0 + r) * DIN_ + v * 8;
        dstA = sb + r * A_ROW_B + v * 16;
    }
    const __half* srcB[2];
    uint32_t dstB[2];
#pragma unroll
    for (int q = 0; q < 2; ++q) {
        int idx = q * NTHREADS + tid;          // q=1 valid only for tid<256
        int w = idx >> 8;                       // 0..2
        int n = (idx >> 2) & 63;
        int v = idx & 3;
        if (w > 2) w = 2;                       // clamp (unused lanes predicated)
        srcB[q] = g_wh + ((size_t)w * M_ + m0 + n) * DIN_ + v * 8;
        dstB[q] = sb + STAGE_A + w * 5120 + n * A_ROW_B + v * 16;
    }
    const bool b1_active = (tid < 256);

    // ---- hoisted ldmatrix row offsets --------------------------------------
    const int rsub = (lane & 7) + 8 * ((lane >> 3) & 1);
    const int ksub2 = 16 * (lane >> 4);           // ksub * 2 bytes
    uint32_t aRow[2];
#pragma unroll
    for (int ts = 0; ts < 2; ++ts)
        aRow[ts] = (uint32_t)((wt * 32 + ts * 16 + rsub) * A_ROW_B) + ksub2;
    const uint32_t bRow =
        (uint32_t)(STAGE_A + (wm * 16 + rsub) * A_ROW_B) + ksub2;

    float acc[3][2][2][4];
#pragma unroll
    for (int w = 0; w < 3; ++w)
#pragma unroll
        for (int ts = 0; ts < 2; ++ts)
#pragma unroll
            for (int nt = 0; nt < 2; ++nt)
#pragma unroll
                for (int f = 0; f < 4; ++f) acc[w][ts][nt][f] = 0.f;

    auto issue_load = [&](int ic, int stg) {
        const uint32_t so = stg * STAGE_BYTES;
        const size_t ko = (size_t)ic * KC;
        cp_async16(dstA + so, srcA + ko);
        cp_async16(dstB[0] + so, srcB[0] + ko);
        if (b1_active) cp_async16(dstB[1] + so, srcB[1] + ko);
    };
    auto issue_pair = [&](int p) {
        issue_load(2 * p, (2 * p) % NSTAGES);
        issue_load(2 * p + 1, (2 * p + 1) % NSTAGES);
        asm volatile("cp.async.commit_group;" ::: "memory");
    };

    auto compute = [&](int stg) {
        const uint32_t base = sb + stg * STAGE_BYTES;
#pragma unroll
        for (int kk = 0; kk < 2; ++kk) {
            const uint32_t kb = base + kk * 32;
            uint32_t ah[2][4];
#pragma unroll
            for (int ts = 0; ts < 2; ++ts)
                ldsm_x4(ah[ts], kb + aRow[ts]);
            uint32_t bf[3][2][2];
#pragma unroll
            for (int w = 0; w < 3; ++w) {
                uint32_t r4[4];
                ldsm_x4(r4, kb + w * 5120 + bRow);
                bf[w][0][0] = r4[0];
                bf[w][1][0] = r4[1];
                bf[w][0][1] = r4[2];
                bf[w][1][1] = r4[3];
            }
#pragma unroll
            for (int w = 0; w < 3; ++w)
#pragma unroll
                for (int ts = 0; ts < 2; ++ts)
#pragma unroll
                    for (int nt = 0; nt < 2; ++nt)
                        mma16816(acc[w][ts][nt], ah[ts], bf[w][nt]);
        }
    };

    issue_pair(0);
    issue_pair(1);
#pragma unroll 1
    for (int p = 0; p < NPAIR; ++p) {
        if (p < NPAIR - 1)
            asm volatile("cp.async.wait_group 1;" ::: "memory");
        else
            asm volatile("cp.async.wait_group 0;" ::: "memory");
        __syncthreads();
        if (p + 2 < NPAIR) issue_pair(p + 2);
        compute((2 * p) % NSTAGES);
        compute((2 * p + 1) % NSTAGES);
    }
    __syncthreads();   // all compute done before smem reuse by epilogue

    // ---- fused epilogue: bias + fast softplus/exp, then t-scan ----
    float* salpha = (float*)smem;                      // [128][66]
    float* sdrive = (float*)(smem + 33792);            // [128][66]
    float* sAp = (float*)(smem + 67584);               // [8][64]
    float* sDp = (float*)(smem + 67584 + 2048);        // [8][64]

#pragma unroll
    for (int ts = 0; ts < 2; ++ts) {
#pragma unroll
        for (int nt = 0; nt < 2; ++nt) {
            const int mloc = wm * 16 + nt * 8 + 2 * (lane & 3);
            const float2 bl = *(const float2*)&b_lam[m0 + mloc];
            const float2 bd = *(const float2*)&b_delt[m0 + mloc];
            const float2 bi = *(const float2*)&b_inp[m0 + mloc];
#pragma unroll
            for (int h = 0; h < 2; ++h) {
                const int t = wt * 32 + ts * 16 + h * 8 + (lane >> 2);
#pragma unroll
                for (int c = 0; c < 2; ++c) {
                    float zl = acc[0][ts][nt][h * 2 + c] + (c ? bl.y : bl.x);
                    float zd = acc[1][ts][nt][h * 2 + c] + (c ? bd.y : bd.x);
                    float zi = acc[2][ts][nt][h * 2 + c] + (c ? bi.y : bi.x);
                    float lamv = softplus_fast(zl);
                    float dlv = softplus_fast(zd);
                    salpha[t * 66 + mloc + c] = __expf(-dlv * lamv);
                    sdrive[t * 66 + mloc + c] = dlv * zi;
                }
            }
        }
    }
    __syncthreads();
    {
        const int m = tid & 63;
        const int ty = tid >> 6;     // 0..7, each 16 t's
        float A = 1.f, D = 0.f;
#pragma unroll
        for (int r = 0; r < 16; ++r) {
            int t = ty * 16 + r;
            float a = salpha[t * 66 + m];
            D = a * D + sdrive[t * 66 + m];
            A *= a;
        }
        sAp[ty * 64 + m] = A;
        sDp[ty * 64 + m] = D;
    }
    __syncthreads();
    if (tid < 64) {
        float A = 1.f, D = 0.f;
#pragma unroll
        for (int r = 0; r < 8; ++r) {
            float a = sAp[r * 64 + tid];
            D = a * D + sDp[r * 64 + tid];
            A *= a;
        }
        size_t o = (size_t)tb * M_ + m0 + tid;
        g_A[o] = A;
        g_D[o] = D;
    }
}

// ---------------------------------------------------------------------------
// Kernel C: combine 16 t-tiles per (b,m), then add_pred[b] = s . W_add + b_add
// ---------------------------------------------------------------------------
__global__ void combine_kernel(const float* __restrict__ W_add,
                               const float* __restrict__ b_add,
                               float* __restrict__ out) {
    int b = blockIdx.x;
    int m = threadIdx.x;
    float s = 0.f;
#pragma unroll
    for (int tt = 0; tt < NTT2; ++tt) {
        size_t idx = ((size_t)(b * NTT2 + tt)) * M_ + m;
        s = g_A[idx] * s + g_D[idx];
    }
    float v = s * W_add[m];
    __shared__ float red[32];
    for (int off = 16; off > 0; off >>= 1)
        v += __shfl_down_sync(0xffffffffu, v, off);
    if ((m & 31) == 0) red[m >> 5] = v;
    __syncthreads();
    if (m < 32) {
        float w = red[m];
        for (int off = 16; off > 0; off >>= 1)
            w += __shfl_down_sync(0xffffffffu, w, off);
        if (m == 0) out[2 * B_ + b] = w + b_add[0];
    }
}

// ---------------------------------------------------------------------------
// Kernel P: parity path, coalesced. 512 threads per b.
// k = tid&63 (consecutive within warp -> coalesced W_theta rows),
// q = tid>>6 owns d in [q*64, q*64+64). Partials reduced via smem.
// ---------------------------------------------------------------------------
__global__ void parity_kernel(const float* __restrict__ W_theta,
                              const float* __restrict__ b_theta,
                              const float* __restrict__ W_par,
                              const float* __restrict__ b_par,
                              float* __restrict__ out) {
    int b = blockIdx.x;
    int tid = threadIdx.x;
    __shared__ double xs[DIN_];
    {
        double s = 0.0;
#pragma unroll
        for (int seg = 0; seg < NSEG; ++seg)
            s += (double)g_xsp[((size_t)seg * B_ + b) * DIN_ + tid];
        xs[tid] = s;
    }
    __syncthreads();
    const int k = tid & 63;
    const int q = tid >> 6;
    double a0 = 0.0, a1 = 0.0;
    const int dbase = q * 64;
#pragma unroll 8
    for (int i = 0; i < 64; i += 2) {
        a0 += xs[dbase + i] * (double)W_theta[(dbase + i) * K_ + k];
        a1 += xs[dbase + i + 1] * (double)W_theta[(dbase + i + 1) * K_ + k];
    }
    __shared__ double part[8][K_];
    part[q][k] = a0 + a1;
    __syncthreads();
    __shared__ float gf[2 * K_];
    if (tid < K_) {
        double acc = 0.0;
#pragma unroll
        for (int r = 0; r < 8; ++r) acc += part[r][tid];
        acc += (double)T_ * (double)b_theta[tid];
        double ang = 3.14159265358979323846 * acc;
        double sn, cs;
        sincos(ang, &sn, &cs);
        gf[tid] = (float)cs;
        gf[K_ + tid] = (float)sn;
    }
    __syncthreads();
    if (tid < 2) {
        float l = b_par[tid];
        for (int j = 0; j < 2 * K_; ++j)
            l += gf[j] * W_par[j * 2 + tid];
        out[b * 2 + tid] = l;
    }
}

// ---------------------------------------------------------------------------
extern "C" void kernel_launch(void* const* d_in, const int* in_sizes, int n_in,
                              void* d_out, int out_size) {
    const float* x       = (const float*)d_in[0];
    const float* W_theta = (const float*)d_in[1];
    const float* b_theta = (const float*)d_in[2];
    const float* W_lam   = (const float*)d_in[3];
    const float* b_lam   = (const float*)d_in[4];
    const float* W_delt  = (const float*)d_in[5];
    const float* b_delt  = (const float*)d_in[6];
    const float* W_inp   = (const float*)d_in[7];
    const float* b_inp   = (const float*)d_in[8];
    const float* W_par   = (const float*)d_in[9];
    const float* b_par   = (const float*)d_in[10];
    const float* W_add   = (const float*)d_in[11];
    const float* b_add   = (const float*)d_in[12];
    float* out = (float*)d_out;

    static int smem_set = 0;
    if (!smem_set) {
        cudaFuncSetAttribute(gssm_mma_kernel,
                             cudaFuncAttributeMaxDynamicSharedMemorySize,
                             SMEM_BYTES);
        smem_set = 1;
    }

    // Prep: fused x convert + partial sums; W transpose
    xprep_kernel<<<dim3(B_, NSEG), 128>>>(x);
    wtsplit_kernel<<<dim3(32, 16, 3), 256>>>(W_lam, W_delt, W_inp);

    // Main fused tensor-core GEMM + scan-reduce (R8 structure)
    gssm_mma_kernel<<<dim3(NMB, B_ * NTT2), NTHREADS, SMEM_BYTES>>>(
        b_lam, b_delt, b_inp);

    // Heads
    parity_kernel<<<B_, DIN_>>>(W_theta, b_theta, W_par, b_par, out);
    combine_kernel<<<B_, M_>>>(W_add, b_add, out);
}

// round 12
// speedup vs baseline: 2.7183x; 1.0832x over previous
#include <cuda_runtime.h>
#include <cuda_fp16.h>
#include <math.h>
#include <stdint.h>

// ---------------------------------------------------------------------------
// GSSM — HMMA fp16, round 12: persistent streaming main kernel.
// R11 decomposition: main ~815us vs 708us MMA floor; gap = 55 waves x ~1.9us
// CTA-boundary overhead, dominated by the cold-prologue load latency of each
// new CTA. Fix: persistent CTAs (grid = #SMs); the cp.async ring streams
// continuously across tile boundaries (pairs 0,1 of tile i+1 issued during
// pairs 6,7 of tile i), epilogue runs from a dedicated smem region while next
// tile's loads are in flight. Parity: fp32 dual-chain partial dots (fp64 only
// for combine+sincos) to kill the DFMA latency chains.
//
// Inputs (metadata order):
//  0: x(32,2048,512) 1: W_theta(512,64) 2: b_theta(64)
//  3: W_lam(512,1024) 4: b_lam 5: W_delt 6: b_delt 7: W_inp 8: b_inp
//  9: W_par(128,2) 10: b_par(2) 11: W_add(1024,1) 12: b_add(1)
// Output: parity_logits (32,2) at [0,64), add_pred (32,1) at [64,96)
// ---------------------------------------------------------------------------

#define B_ 32
#define T_ 2048
#define DIN_ 512
#define M_ 1024
#define K_ 64

#define TB 128               // t rows per tile
#define MB 64                // m cols per tile
#define KC 32                // k per sub-chunk
#define NPAIR 8              // 16 sub-chunks = 8 pairs per tile
#define NTT2 (T_ / TB)       // 16 t-tiles per batch
#define NMB (M_ / MB)        // 16 m-tiles
#define NTILES (NMB * B_ * NTT2)   // 8192
#define NSEG 32              // xs reduction segments

#define NTHREADS 512

// smem sub-stage layout (fp16, padded rows of 40 elems = 80 B):
//   A: [128 rows][40]  = 10240 B ; B: [3 w][64 rows][40] = 15360 B
#define A_ROW_B 80
#define STAGE_A 10240
#define STAGE_BYTES 25600
#define RING_BYTES (STAGE_BYTES * 6)         // 153600 (3 pair-slots)
#define EPI_OFF RING_BYTES                   // dedicated epilogue region
#define SMEM_BYTES (RING_BYTES + 71680)      // 225280

// ---- static device scratch (no allocation allowed) ------------------------
__device__ __half g_xh[(size_t)B_ * T_ * DIN_];
__device__ __half g_wh[3u * M_ * DIN_];    // [w][m][k] K-major, fp16
__device__ float g_A[B_ * NTT2 * M_];
__device__ float g_D[B_ * NTT2 * M_];
__device__ float g_xsp[NSEG * B_ * DIN_];  // fp32 partial sums of x over T segs

// ---- helpers ---------------------------------------------------------------
__device__ __forceinline__ uint32_t smem_u32(const void* p) {
    uint32_t a;
    asm("{ .reg .u64 t; cvta.to.shared.u64 t, %1; cvt.u32.u64 %0, t; }"
        : "=r"(a) : "l"(p));
    return a;
}

__device__ __forceinline__ void cp_async16(uint32_t dst, const void* src) {
    asm volatile("cp.async.cg.shared.global [%0], [%1], 16;"
                 :: "r"(dst), "l"(src) : "memory");
}

__device__ __forceinline__ void ldsm_x4(uint32_t* r, uint32_t addr) {
    asm volatile("ldmatrix.sync.aligned.m8n8.x4.shared.b16 {%0,%1,%2,%3}, [%4];"
                 : "=r"(r[0]), "=r"(r[1]), "=r"(r[2]), "=r"(r[3]) : "r"(addr));
}

__device__ __forceinline__ void mma16816(float* d, const uint32_t* a,
                                         const uint32_t* b) {
    asm volatile(
        "mma.sync.aligned.m16n8k16.row.col.f32.f16.f16.f32 "
        "{%0,%1,%2,%3}, {%4,%5,%6,%7}, {%8,%9}, {%0,%1,%2,%3};"
        : "+f"(d[0]), "+f"(d[1]), "+f"(d[2]), "+f"(d[3])
        : "r"(a[0]), "r"(a[1]), "r"(a[2]), "r"(a[3]), "r"(b[0]), "r"(b[1]));
}

__device__ __forceinline__ float softplus_fast(float z) {
    float e = __expf(-fabsf(z));
    return fmaxf(z, 0.0f) + __logf(1.0f + e);
}

// ---------------------------------------------------------------------------
// Prep 1 (fused): x -> fp16, and fp32 partial sums over 32 T-segments.
// ---------------------------------------------------------------------------
__global__ void xprep_kernel(const float* __restrict__ x) {
    const int b = blockIdx.x;
    const int seg = blockIdx.y;
    const int d0 = threadIdx.x * 4;
    const int TS = T_ / NSEG;   // 64
    const float* xp = x + ((size_t)b * T_ + (size_t)seg * TS) * DIN_ + d0;
    __half* hp = g_xh + ((size_t)b * T_ + (size_t)seg * TS) * DIN_ + d0;
    float s0 = 0.f, s1 = 0.f, s2 = 0.f, s3 = 0.f;
#pragma unroll 4
    for (int t = 0; t < TS; ++t) {
        float4 v = *(const float4*)(xp + (size_t)t * DIN_);
        s0 += v.x; s1 += v.y; s2 += v.z; s3 += v.w;
        __align__(8) __half h[4] = {__float2half(v.x), __float2half(v.y),
                                    __float2half(v.z), __float2half(v.w)};
        *(uint2*)(hp + (size_t)t * DIN_) = *(const uint2*)h;
    }
    float4 out = make_float4(s0, s1, s2, s3);
    *(float4*)&g_xsp[((size_t)seg * B_ + b) * DIN_ + d0] = out;
}

// ---------------------------------------------------------------------------
// Prep 2: transpose W (512x1024 f32) -> [w][m][k] fp16
// ---------------------------------------------------------------------------
__global__ void wtsplit_kernel(const float* __restrict__ Wl,
                               const float* __restrict__ Wd,
                               const float* __restrict__ Wi) {
    __shared__ float tile[32][33];
    const int w = blockIdx.z;
    const float* W = (w == 0) ? Wl : ((w == 1) ? Wd : Wi);
    const int m0 = blockIdx.x * 32;
    const int k0 = blockIdx.y * 32;
    const int tx = threadIdx.x & 31;
    const int ty = threadIdx.x >> 5;
#pragma unroll
    for (int r = 0; r < 4; ++r)
        tile[ty + 8 * r][tx] = W[(size_t)(k0 + ty + 8 * r) * M_ + m0 + tx];
    __syncthreads();
#pragma unroll
    for (int r = 0; r < 4; ++r) {
        int m = ty + 8 * r;
        int k = tx;
        size_t o = ((size_t)w * M_ + m0 + m) * DIN_ + k0 + k;
        g_wh[o] = __float2half(tile[k][m]);
    }
}

// ---------------------------------------------------------------------------
// Main persistent kernel: HMMA fp16 triple-GEMM, streaming cp.async ring
// across tiles, fused MUFU epilogue + t-scan.
// grid = #SMs, 512 threads (16 warps: 4 t x 4 m). Tile g: mb=g&15, tb=g>>4.
// ---------------------------------------------------------------------------
__global__ void __launch_bounds__(NTHREADS, 1)
gssm_mma_kernel(const float* __restrict__ b_lam,
                const float* __restrict__ b_delt,
                const float* __restrict__ b_inp) {
    extern __shared__ __align__(128) char smem[];
    const uint32_t sb = smem_u32(smem);
    const int tid = threadIdx.x;
    const int lane = tid & 31;
    const int wid = tid >> 5;
    const int wt = wid & 3;        // t-quadrant: rows wt*32..+31
    const int wm = wid >> 2;       // m-sixteenth: cols wm*16..+15

    // ---- per-thread constant load offsets (tile base added per tile) -------
    const size_t constA = (size_t)(tid >> 2) * DIN_ + (size_t)(tid & 3) * 8;
    const uint32_t dstA = sb + (tid >> 2) * A_ROW_B + (tid & 3) * 16;
    size_t constB[2];
    uint32_t dstB[2];
#pragma unroll
    for (int q = 0; q < 2; ++q) {
        int idx = q * NTHREADS + tid;
        int w = idx >> 8;
        int n = (idx >> 2) & 63;
        int v = idx & 3;
        if (w > 2) w = 2;
        constB[q] = ((size_t)w * M_ + n) * DIN_ + (size_t)v * 8;
        dstB[q] = sb + STAGE_A + w * 5120 + n * A_ROW_B + v * 16;
    }
    const bool b1_active = (tid < 256);

    // ---- hoisted ldmatrix row offsets --------------------------------------
    const int rsub = (lane & 7) + 8 * ((lane >> 3) & 1);
    const int ksub2 = 16 * (lane >> 4);
    uint32_t aRow[2];
#pragma unroll
    for (int ts = 0; ts < 2; ++ts)
        aRow[ts] = (uint32_t)((wt * 32 + ts * 16 + rsub) * A_ROW_B) + ksub2;
    const uint32_t bRow =
        (uint32_t)(STAGE_A + (wm * 16 + rsub) * A_ROW_B) + ksub2;

    // issue one pair (2 sub-chunks) for tile bases (bA, bB) into pair slot
    auto issue_pair = [&](const __half* bA, const __half* bB, int lp, int slot) {
        const uint32_t so0 = (uint32_t)(slot % 3) * (2 * STAGE_BYTES);
        const size_t ko0 = (size_t)(2 * lp) * KC;
#pragma unroll
        for (int c = 0; c < 2; ++c) {
            const uint32_t so = so0 + c * STAGE_BYTES;
            const size_t ko = ko0 + c * KC;
            cp_async16(dstA + so, bA + constA + ko);
            cp_async16(dstB[0] + so, bB + constB[0] + ko);
            if (b1_active) cp_async16(dstB[1] + so, bB + constB[1] + ko);
        }
        asm volatile("cp.async.commit_group;" ::: "memory");
    };

    float acc[3][2][2][4];

    auto compute = [&](int stg) {
        const uint32_t base = sb + stg * STAGE_BYTES;
#pragma unroll
        for (int kk = 0; kk < 2; ++kk) {
            const uint32_t kb = base + kk * 32;
            uint32_t ah[2][4];
#pragma unroll
            for (int ts = 0; ts < 2; ++ts)
                ldsm_x4(ah[ts], kb + aRow[ts]);
            uint32_t bf[3][2][2];
#pragma unroll
            for (int w = 0; w < 3; ++w) {
                uint32_t r4[4];
                ldsm_x4(r4, kb + w * 5120 + bRow);
                bf[w][0][0] = r4[0];
                bf[w][1][0] = r4[1];
                bf[w][0][1] = r4[2];
                bf[w][1][1] = r4[3];
            }
#pragma unroll
            for (int w = 0; w < 3; ++w)
#pragma unroll
                for (int ts = 0; ts < 2; ++ts)
#pragma unroll
                    for (int nt = 0; nt < 2; ++nt)
                        mma16816(acc[w][ts][nt], ah[ts], bf[w][nt]);
        }
    };

    // epilogue smem (dedicated region; never overlaps the ring)
    float* salpha = (float*)(smem + EPI_OFF);            // [128][66]
    float* sdrive = (float*)(smem + EPI_OFF + 33792);    // [128][66]
    float* sAp = (float*)(smem + EPI_OFF + 67584);       // [8][64]
    float* sDp = (float*)(smem + EPI_OFF + 67584 + 2048);// [8][64]

    const int GS = gridDim.x;
    int g0 = blockIdx.x;
    if (g0 >= NTILES) return;

    const __half* curA = g_xh + (size_t)(g0 >> 4) * TB * DIN_;
    const __half* curB = g_wh + (size_t)(g0 & 15) * MB * DIN_;
    int pc = 0;
    issue_pair(curA, curB, 0, pc);
    issue_pair(curA, curB, 1, pc + 1);

#pragma unroll 1
    for (int g = g0; g < NTILES; g += GS) {
        const int gn = g + GS;
        const bool has_next = (gn < NTILES);
        const __half* nxtA =
            has_next ? g_xh + (size_t)(gn >> 4) * TB * DIN_ : curA;
        const __half* nxtB =
            has_next ? g_wh + (size_t)(gn & 15) * MB * DIN_ : curB;
        const int m0 = (g & 15) * MB;

#pragma unroll
        for (int w = 0; w < 3; ++w)
#pragma unroll
            for (int ts = 0; ts < 2; ++ts)
#pragma unroll
                for (int nt = 0; nt < 2; ++nt)
#pragma unroll
                    for (int f = 0; f < 4; ++f) acc[w][ts][nt][f] = 0.f;

#pragma unroll 1
        for (int p = 0; p < NPAIR; ++p) {
            if (!has_next && p == NPAIR - 1)
                asm volatile("cp.async.wait_group 0;" ::: "memory");
            else
                asm volatile("cp.async.wait_group 1;" ::: "memory");
            __syncthreads();
            if (p < 6)
                issue_pair(curA, curB, p + 2, pc + 2);
            else if (has_next)
                issue_pair(nxtA, nxtB, p - 6, pc + 2);
            const int s0 = (pc % 3) * 2;
            compute(s0);
            compute(s0 + 1);
            ++pc;
        }

        // ---- fused epilogue: bias + fast softplus/exp, then t-scan ----
#pragma unroll
        for (int ts = 0; ts < 2; ++ts) {
#pragma unroll
            for (int nt = 0; nt < 2; ++nt) {
                const int mloc = wm * 16 + nt * 8 + 2 * (lane & 3);
                const float2 bl = *(const float2*)&b_lam[m0 + mloc];
                const float2 bd = *(const float2*)&b_delt[m0 + mloc];
                const float2 bi = *(const float2*)&b_inp[m0 + mloc];
#pragma unroll
                for (int h = 0; h < 2; ++h) {
                    const int t = wt * 32 + ts * 16 + h * 8 + (lane >> 2);
#pragma unroll
                    for (int c = 0; c < 2; ++c) {
                        float zl = acc[0][ts][nt][h * 2 + c] + (c ? bl.y : bl.x);
                        float zd = acc[1][ts][nt][h * 2 + c] + (c ? bd.y : bd.x);
                        float zi = acc[2][ts][nt][h * 2 + c] + (c ? bi.y : bi.x);
                        float lamv = softplus_fast(zl);
                        float dlv = softplus_fast(zd);
                        salpha[t * 66 + mloc + c] = __expf(-dlv * lamv);
                        sdrive[t * 66 + mloc + c] = dlv * zi;
                    }
                }
            }
        }
        __syncthreads();
        {
            const int m = tid & 63;
            const int ty = tid >> 6;     // 0..7, each 16 t's
            float A = 1.f, D = 0.f;
#pragma unroll
            for (int r = 0; r < 16; ++r) {
                int t = ty * 16 + r;
                float a = salpha[t * 66 + m];
                D = a * D + sdrive[t * 66 + m];
                A *= a;
            }
            sAp[ty * 64 + m] = A;
            sDp[ty * 64 + m] = D;
        }
        __syncthreads();
        if (tid < 64) {
            float A = 1.f, D = 0.f;
#pragma unroll
            for (int r = 0; r < 8; ++r) {
                float a = sAp[r * 64 + tid];
                D = a * D + sDp[r * 64 + tid];
                A *= a;
            }
            size_t o = (size_t)(g >> 4) * M_ + m0 + tid;
            g_A[o] = A;
            g_D[o] = D;
        }
        curA = nxtA;
        curB = nxtB;
    }
}

// ---------------------------------------------------------------------------
// Kernel C: combine 16 t-tiles per (b,m), then add_pred[b] = s . W_add + b_add
// ---------------------------------------------------------------------------
__global__ void combine_kernel(const float* __restrict__ W_add,
                               const float* __restrict__ b_add,
                               float* __restrict__ out) {
    int b = blockIdx.x;
    int m = threadIdx.x;
    float s = 0.f;
#pragma unroll
    for (int tt = 0; tt < NTT2; ++tt) {
        size_t idx = ((size_t)(b * NTT2 + tt)) * M_ + m;
        s = g_A[idx] * s + g_D[idx];
    }
    float v = s * W_add[m];
    __shared__ float red[32];
    for (int off = 16; off > 0; off >>= 1)
        v += __shfl_down_sync(0xffffffffu, v, off);
    if ((m & 31) == 0) red[m >> 5] = v;
    __syncthreads();
    if (m < 32) {
        float w = red[m];
        for (int off = 16; off > 0; off >>= 1)
            w += __shfl_down_sync(0xffffffffu, w, off);
        if (m == 0) out[2 * B_ + b] = w + b_add[0];
    }
}

// ---------------------------------------------------------------------------
// Kernel P: parity path. fp32 partial dots (dual-chain), fp64 combine+sincos.
// 512 threads per b: k = tid&63 (coalesced W_theta), q = tid>>6 owns 64 d's.
// ---------------------------------------------------------------------------
__global__ void parity_kernel(const float* __restrict__ W_theta,
                              const float* __restrict__ b_theta,
                              const float* __restrict__ W_par,
                              const float* __restrict__ b_par,
                              float* __restrict__ out) {
    int b = blockIdx.x;
    int tid = threadIdx.x;
    __shared__ float xs[DIN_];
    {
        float s0 = 0.f, s1 = 0.f, s2 = 0.f, s3 = 0.f;
#pragma unroll
        for (int seg = 0; seg < NSEG; seg += 4) {
            s0 += g_xsp[((size_t)(seg + 0) * B_ + b) * DIN_ + tid];
            s1 += g_xsp[((size_t)(seg + 1) * B_ + b) * DIN_ + tid];
            s2 += g_xsp[((size_t)(seg + 2) * B_ + b) * DIN_ + tid];
            s3 += g_xsp[((size_t)(seg + 3) * B_ + b) * DIN_ + tid];
        }
        xs[tid] = (s0 + s1) + (s2 + s3);
    }
    __syncthreads();
    const int k = tid & 63;
    const int q = tid >> 6;
    float a0 = 0.f, a1 = 0.f;
    const int dbase = q * 64;
#pragma unroll 8
    for (int i = 0; i < 64; i += 2) {
        a0 = fmaf(xs[dbase + i], W_theta[(dbase + i) * K_ + k], a0);
        a1 = fmaf(xs[dbase + i + 1], W_theta[(dbase + i + 1) * K_ + k], a1);
    }
    __shared__ float part[8][K_];
    part[q][k] = a0 + a1;
    __syncthreads();
    __shared__ float gf[2 * K_];
    if (tid < K_) {
        double acc = 0.0;
#pragma unroll
        for (int r = 0; r < 8; ++r) acc += (double)part[r][tid];
        acc += (double)T_ * (double)b_theta[tid];
        double ang = 3.14159265358979323846 * acc;
        double sn, cs;
        sincos(ang, &sn, &cs);
        gf[tid] = (float)cs;
        gf[K_ + tid] = (float)sn;
    }
    __syncthreads();
    if (tid < 2) {
        float l = b_par[tid];
        for (int j = 0; j < 2 * K_; ++j)
            l += gf[j] * W_par[j * 2 + tid];
        out[b * 2 + tid] = l;
    }
}

// ---------------------------------------------------------------------------
extern "C" void kernel_launch(void* const* d_in, const int* in_sizes, int n_in,
                              void* d_out, int out_size) {
    const float* x       = (const float*)d_in[0];
    const float* W_theta = (const float*)d_in[1];
    const float* b_theta = (const float*)d_in[2];
    const float* W_lam   = (const float*)d_in[3];
    const float* b_lam   = (const float*)d_in[4];
    const float* W_delt  = (const float*)d_in[5];
    const float* b_delt  = (const float*)d_in[6];
    const float* W_inp   = (const float*)d_in[7];
    const float* b_inp   = (const float*)d_in[8];
    const float* W_par   = (const float*)d_in[9];
    const float* b_par   = (const float*)d_in[10];
    const float* W_add   = (const float*)d_in[11];
    const float* b_add   = (const float*)d_in[12];
    float* out = (float*)d_out;

    static int nsm = 0;
    if (!nsm) {
        cudaFuncSetAttribute(gssm_mma_kernel,
                             cudaFuncAttributeMaxDynamicSharedMemorySize,
                             SMEM_BYTES);
        if (cudaDeviceGetAttribute(&nsm, cudaDevAttrMultiProcessorCount, 0)
                != cudaSuccess || nsm <= 0)
            nsm = 148;
    }

    // Prep: fused x convert + partial sums; W transpose
    xprep_kernel<<<dim3(B_, NSEG), 128>>>(x);
    wtsplit_kernel<<<dim3(32, 16, 3), 256>>>(W_lam, W_delt, W_inp);

    // Main fused tensor-core GEMM + scan-reduce (persistent streaming)
    gssm_mma_kernel<<<nsm, NTHREADS, SMEM_BYTES>>>(b_lam, b_delt, b_inp);

    // Heads
    parity_kernel<<<B_, DIN_>>>(W_theta, b_theta, W_par, b_par, out);
    combine_kernel<<<B_, M_>>>(W_add, b_add, out);
}

// round 13
// speedup vs baseline: 2.7472x; 1.0106x over previous
#include <cuda_runtime.h>
#include <cuda_fp16.h>
#include <math.h>
#include <stdint.h>

// ---------------------------------------------------------------------------
// GSSM — HMMA fp16, round 13: scan hidden under next tile's MMAs.
// R12 calibration: main kernel at 93-98% of the 512 MAC/cyc/SM legacy-HMMA
// ceiling. Residues: per-tile scan phases + 2 barriers (~10us), softplus ALU
// (~5us), aux kernels (~91us). This round: tile g's scan phase-2/3 executes
// inside tile g+1's pair-loop (after the p=0 / p=1 barriers — existing syncs
// provide the ordering), unstable-form softplus (|z|<~4 so safe), higher-MLP
// xprep/parity, parity+combine merged into one launch.
//
// Inputs (metadata order):
//  0: x(32,2048,512) 1: W_theta(512,64) 2: b_theta(64)
//  3: W_lam(512,1024) 4: b_lam 5: W_delt 6: b_delt 7: W_inp 8: b_inp
//  9: W_par(128,2) 10: b_par(2) 11: W_add(1024,1) 12: b_add(1)
// Output: parity_logits (32,2) at [0,64), add_pred (32,1) at [64,96)
// ---------------------------------------------------------------------------

#define B_ 32
#define T_ 2048
#define DIN_ 512
#define M_ 1024
#define K_ 64

#define TB 128               // t rows per tile
#define MB 64                // m cols per tile
#define KC 32                // k per sub-chunk
#define NPAIR 8              // 16 sub-chunks = 8 pairs per tile
#define NTT2 (T_ / TB)       // 16 t-tiles per batch
#define NMB (M_ / MB)        // 16 m-tiles
#define NTILES (NMB * B_ * NTT2)   // 8192
#define NSEG 64              // xs reduction segments (TS = 32)

#define NTHREADS 512

// smem sub-stage layout (fp16, padded rows of 40 elems = 80 B):
//   A: [128 rows][40]  = 10240 B ; B: [3 w][64 rows][40] = 15360 B
#define A_ROW_B 80
#define STAGE_A 10240
#define STAGE_BYTES 25600
#define RING_BYTES (STAGE_BYTES * 6)         // 153600 (3 pair-slots)
#define EPI_OFF RING_BYTES                   // dedicated epilogue region
#define SMEM_BYTES (RING_BYTES + 71680)      // 225280

// ---- static device scratch (no allocation allowed) ------------------------
__device__ __half g_xh[(size_t)B_ * T_ * DIN_];
__device__ __half g_wh[3u * M_ * DIN_];    // [w][m][k] K-major, fp16
__device__ float g_A[B_ * NTT2 * M_];
__device__ float g_D[B_ * NTT2 * M_];
__device__ float g_xsp[NSEG * B_ * DIN_];  // fp32 partial sums of x over T segs

// ---- helpers ---------------------------------------------------------------
__device__ __forceinline__ uint32_t smem_u32(const void* p) {
    uint32_t a;
    asm("{ .reg .u64 t; cvta.to.shared.u64 t, %1; cvt.u32.u64 %0, t; }"
        : "=r"(a) : "l"(p));
    return a;
}

__device__ __forceinline__ void cp_async16(uint32_t dst, const void* src) {
    asm volatile("cp.async.cg.shared.global [%0], [%1], 16;"
                 :: "r"(dst), "l"(src) : "memory");
}

__device__ __forceinline__ void ldsm_x4(uint32_t* r, uint32_t addr) {
    asm volatile("ldmatrix.sync.aligned.m8n8.x4.shared.b16 {%0,%1,%2,%3}, [%4];"
                 : "=r"(r[0]), "=r"(r[1]), "=r"(r[2]), "=r"(r[3]) : "r"(addr));
}

__device__ __forceinline__ void mma16816(float* d, const uint32_t* a,
                                         const uint32_t* b) {
    asm volatile(
        "mma.sync.aligned.m16n8k16.row.col.f32.f16.f16.f32 "
        "{%0,%1,%2,%3}, {%4,%5,%6,%7}, {%8,%9}, {%0,%1,%2,%3};"
        : "+f"(d[0]), "+f"(d[1]), "+f"(d[2]), "+f"(d[3])
        : "r"(a[0]), "r"(a[1]), "r"(a[2]), "r"(a[3]), "r"(b[0]), "r"(b[1]));
}

// |z| <= ~4 here (sigma_z=0.577, biases ~0.04), so the unstable form is safe
__device__ __forceinline__ float softplus_fast(float z) {
    return __logf(1.0f + __expf(z));
}

// ---------------------------------------------------------------------------
// Prep 1 (fused): x -> fp16, and fp32 partial sums over 64 T-segments.
// grid (B_, NSEG), 128 threads; thread owns 4 consecutive d columns.
// ---------------------------------------------------------------------------
__global__ void xprep_kernel(const float* __restrict__ x) {
    const int b = blockIdx.x;
    const int seg = blockIdx.y;
    const int d0 = threadIdx.x * 4;
    const int TS = T_ / NSEG;   // 32
    const float* xp = x + ((size_t)b * T_ + (size_t)seg * TS) * DIN_ + d0;
    __half* hp = g_xh + ((size_t)b * T_ + (size_t)seg * TS) * DIN_ + d0;
    float s0 = 0.f, s1 = 0.f, s2 = 0.f, s3 = 0.f;
#pragma unroll 8
    for (int t = 0; t < TS; ++t) {
        float4 v = *(const float4*)(xp + (size_t)t * DIN_);
        s0 += v.x; s1 += v.y; s2 += v.z; s3 += v.w;
        __align__(8) __half h[4] = {__float2half(v.x), __float2half(v.y),
                                    __float2half(v.z), __float2half(v.w)};
        *(uint2*)(hp + (size_t)t * DIN_) = *(const uint2*)h;
    }
    float4 out = make_float4(s0, s1, s2, s3);
    *(float4*)&g_xsp[((size_t)seg * B_ + b) * DIN_ + d0] = out;
}

// ---------------------------------------------------------------------------
// Prep 2: transpose W (512x1024 f32) -> [w][m][k] fp16
// ---------------------------------------------------------------------------
__global__ void wtsplit_kernel(const float* __restrict__ Wl,
                               const float* __restrict__ Wd,
                               const float* __restrict__ Wi) {
    __shared__ float tile[32][33];
    const int w = blockIdx.z;
    const float* W = (w == 0) ? Wl : ((w == 1) ? Wd : Wi);
    const int m0 = blockIdx.x * 32;
    const int k0 = blockIdx.y * 32;
    const int tx = threadIdx.x & 31;
    const int ty = threadIdx.x >> 5;
#pragma unroll
    for (int r = 0; r < 4; ++r)
        tile[ty + 8 * r][tx] = W[(size_t)(k0 + ty + 8 * r) * M_ + m0 + tx];
    __syncthreads();
#pragma unroll
    for (int r = 0; r < 4; ++r) {
        int m = ty + 8 * r;
        int k = tx;
        size_t o = ((size_t)w * M_ + m0 + m) * DIN_ + k0 + k;
        g_wh[o] = __float2half(tile[k][m]);
    }
}

// ---------------------------------------------------------------------------
// Main persistent kernel: HMMA fp16 triple-GEMM, streaming cp.async ring
// across tiles, MUFU epilogue; the t-scan of tile g runs inside tile g+1's
// pair loop (p=0: phase-2, p=1: phase-3), hidden under MMAs.
// ---------------------------------------------------------------------------
__global__ void __launch_bounds__(NTHREADS, 1)
gssm_mma_kernel(const float* __restrict__ b_lam,
                const float* __restrict__ b_delt,
                const float* __restrict__ b_inp) {
    extern __shared__ __align__(128) char smem[];
    const uint32_t sb = smem_u32(smem);
    const int tid = threadIdx.x;
    const int lane = tid & 31;
    const int wid = tid >> 5;
    const int wt = wid & 3;        // t-quadrant: rows wt*32..+31
    const int wm = wid >> 2;       // m-sixteenth: cols wm*16..+15

    // ---- per-thread constant load offsets (tile base added per tile) -------
    const size_t constA = (size_t)(tid >> 2) * DIN_ + (size_t)(tid & 3) * 8;
    const uint32_t dstA = sb + (tid >> 2) * A_ROW_B + (tid & 3) * 16;
    size_t constB[2];
    uint32_t dstB[2];
#pragma unroll
    for (int q = 0; q < 2; ++q) {
        int idx = q * NTHREADS + tid;
        int w = idx >> 8;
        int n = (idx >> 2) & 63;
        int v = idx & 3;
        if (w > 2) w = 2;
        constB[q] = ((size_t)w * M_ + n) * DIN_ + (size_t)v * 8;
        dstB[q] = sb + STAGE_A + w * 5120 + n * A_ROW_B + v * 16;
    }
    const bool b1_active = (tid < 256);

    // ---- hoisted ldmatrix row offsets --------------------------------------
    const int rsub = (lane & 7) + 8 * ((lane >> 3) & 1);
    const int ksub2 = 16 * (lane >> 4);
    uint32_t aRow[2];
#pragma unroll
    for (int ts = 0; ts < 2; ++ts)
        aRow[ts] = (uint32_t)((wt * 32 + ts * 16 + rsub) * A_ROW_B) + ksub2;
    const uint32_t bRow =
        (uint32_t)(STAGE_A + (wm * 16 + rsub) * A_ROW_B) + ksub2;

    auto issue_pair = [&](const __half* bA, const __half* bB, int lp, int slot) {
        const uint32_t so0 = (uint32_t)(slot % 3) * (2 * STAGE_BYTES);
        const size_t ko0 = (size_t)(2 * lp) * KC;
#pragma unroll
        for (int c = 0; c < 2; ++c) {
            const uint32_t so = so0 + c * STAGE_BYTES;
            const size_t ko = ko0 + c * KC;
            cp_async16(dstA + so, bA + constA + ko);
            cp_async16(dstB[0] + so, bB + constB[0] + ko);
            if (b1_active) cp_async16(dstB[1] + so, bB + constB[1] + ko);
        }
        asm volatile("cp.async.commit_group;" ::: "memory");
    };

    float acc[3][2][2][4];

    auto compute = [&](int stg) {
        const uint32_t base = sb + stg * STAGE_BYTES;
#pragma unroll
        for (int kk = 0; kk < 2; ++kk) {
            const uint32_t kb = base + kk * 32;
            uint32_t ah[2][4];
#pragma unroll
            for (int ts = 0; ts < 2; ++ts)
                ldsm_x4(ah[ts], kb + aRow[ts]);
            uint32_t bf[3][2][2];
#pragma unroll
            for (int w = 0; w < 3; ++w) {
                uint32_t r4[4];
                ldsm_x4(r4, kb + w * 5120 + bRow);
                bf[w][0][0] = r4[0];
                bf[w][1][0] = r4[1];
                bf[w][0][1] = r4[2];
                bf[w][1][1] = r4[3];
            }
#pragma unroll
            for (int w = 0; w < 3; ++w)
#pragma unroll
                for (int ts = 0; ts < 2; ++ts)
#pragma unroll
                    for (int nt = 0; nt < 2; ++nt)
                        mma16816(acc[w][ts][nt], ah[ts], bf[w][nt]);
        }
    };

    // epilogue smem (dedicated region; never overlaps the ring)
    float* salpha = (float*)(smem + EPI_OFF);            // [128][66]
    float* sdrive = (float*)(smem + EPI_OFF + 33792);    // [128][66]
    float* sAp = (float*)(smem + EPI_OFF + 67584);       // [8][64]
    float* sDp = (float*)(smem + EPI_OFF + 67584 + 2048);// [8][64]

    // scan phase-2: 512 threads reduce 16 t's each -> sAp/sDp
    auto scan_p2 = [&]() {
        const int m = tid & 63;
        const int ty = tid >> 6;
        float A = 1.f, D = 0.f;
#pragma unroll
        for (int r = 0; r < 16; ++r) {
            int t = ty * 16 + r;
            float a = salpha[t * 66 + m];
            D = a * D + sdrive[t * 66 + m];
            A *= a;
        }
        sAp[ty * 64 + m] = A;
        sDp[ty * 64 + m] = D;
    };
    // scan phase-3: 64 threads combine 8 segments, store to gmem
    auto scan_p3 = [&](size_t o) {
        if (tid < 64) {
            float A = 1.f, D = 0.f;
#pragma unroll
            for (int r = 0; r < 8; ++r) {
                float a = sAp[r * 64 + tid];
                D = a * D + sDp[r * 64 + tid];
                A *= a;
            }
            g_A[o + tid] = A;
            g_D[o + tid] = D;
        }
    };

    const int GS = gridDim.x;
    int g0 = blockIdx.x;
    if (g0 >= NTILES) return;

    const __half* curA = g_xh + (size_t)(g0 >> 4) * TB * DIN_;
    const __half* curB = g_wh + (size_t)(g0 & 15) * MB * DIN_;
    int pc = 0;
    issue_pair(curA, curB, 0, pc);
    issue_pair(curA, curB, 1, pc + 1);

    int prev_valid = 0;
    size_t prev_o = 0;

#pragma unroll 1
    for (int g = g0; g < NTILES; g += GS) {
        const int gn = g + GS;
        const bool has_next = (gn < NTILES);
        const __half* nxtA =
            has_next ? g_xh + (size_t)(gn >> 4) * TB * DIN_ : curA;
        const __half* nxtB =
            has_next ? g_wh + (size_t)(gn & 15) * MB * DIN_ : curB;
        const int m0 = (g & 15) * MB;

#pragma unroll
        for (int w = 0; w < 3; ++w)
#pragma unroll
            for (int ts = 0; ts < 2; ++ts)
#pragma unroll
                for (int nt = 0; nt < 2; ++nt)
#pragma unroll
                    for (int f = 0; f < 4; ++f) acc[w][ts][nt][f] = 0.f;

#pragma unroll 1
        for (int p = 0; p < NPAIR; ++p) {
            if (!has_next && p == NPAIR - 1)
                asm volatile("cp.async.wait_group 0;" ::: "memory");
            else
                asm volatile("cp.async.wait_group 1;" ::: "memory");
            __syncthreads();
            // hidden scan of the PREVIOUS tile (ordering by the p=0/p=1 syncs)
            if (p == 0 && prev_valid) scan_p2();
            if (p == 1 && prev_valid) scan_p3(prev_o);
            if (p < 6)
                issue_pair(curA, curB, p + 2, pc + 2);
            else if (has_next)
                issue_pair(nxtA, nxtB, p - 6, pc + 2);
            const int s0 = (pc % 3) * 2;
            compute(s0);
            compute(s0 + 1);
            ++pc;
        }

        // ---- epilogue phase-1: bias + MUFU softplus/exp -> salpha/sdrive ---
        // (no barrier needed: next tile's p=0 sync orders these stores)
#pragma unroll
        for (int ts = 0; ts < 2; ++ts) {
#pragma unroll
            for (int nt = 0; nt < 2; ++nt) {
                const int mloc = wm * 16 + nt * 8 + 2 * (lane & 3);
                const float2 bl = *(const float2*)&b_lam[m0 + mloc];
                const float2 bd = *(const float2*)&b_delt[m0 + mloc];
                const float2 bi = *(const float2*)&b_inp[m0 + mloc];
#pragma unroll
                for (int h = 0; h < 2; ++h) {
                    const int t = wt * 32 + ts * 16 + h * 8 + (lane >> 2);
#pragma unroll
                    for (int c = 0; c < 2; ++c) {
                        float zl = acc[0][ts][nt][h * 2 + c] + (c ? bl.y : bl.x);
                        float zd = acc[1][ts][nt][h * 2 + c] + (c ? bd.y : bd.x);
                        float zi = acc[2][ts][nt][h * 2 + c] + (c ? bi.y : bi.x);
                        float lamv = softplus_fast(zl);
                        float dlv = softplus_fast(zd);
                        salpha[t * 66 + mloc + c] = __expf(-dlv * lamv);
                        sdrive[t * 66 + mloc + c] = dlv * zi;
                    }
                }
            }
        }
        prev_valid = 1;
        prev_o = (size_t)(g >> 4) * M_ + m0;
        curA = nxtA;
        curB = nxtB;
    }
    // final tile's scan
    __syncthreads();
    scan_p2();
    __syncthreads();
    scan_p3(prev_o);
}

// ---------------------------------------------------------------------------
// Heads kernel: grid (B_, 2) x 1024 threads.
//  y==0: combine 16 t-tiles per (b,m) -> add_pred[b]
//  y==1: parity path (512 threads): fp32 dual-chain dots, fp64 combine+sincos
// ---------------------------------------------------------------------------
__global__ void heads_kernel(const float* __restrict__ W_theta,
                             const float* __restrict__ b_theta,
                             const float* __restrict__ W_par,
                             const float* __restrict__ b_par,
                             const float* __restrict__ W_add,
                             const float* __restrict__ b_add,
                             float* __restrict__ out) {
    const int b = blockIdx.x;
    const int tid = threadIdx.x;
    if (blockIdx.y == 0) {
        // ---- combine + add head ----
        int m = tid;
        float s = 0.f;
#pragma unroll
        for (int tt = 0; tt < NTT2; ++tt) {
            size_t idx = ((size_t)(b * NTT2 + tt)) * M_ + m;
            s = g_A[idx] * s + g_D[idx];
        }
        float v = s * W_add[m];
        __shared__ float red[32];
        for (int off = 16; off > 0; off >>= 1)
            v += __shfl_down_sync(0xffffffffu, v, off);
        if ((m & 31) == 0) red[m >> 5] = v;
        __syncthreads();
        if (m < 32) {
            float w = red[m];
            for (int off = 16; off > 0; off >>= 1)
                w += __shfl_down_sync(0xffffffffu, w, off);
            if (m == 0) out[2 * B_ + b] = w + b_add[0];
        }
    } else {
        // ---- parity head (512 threads) ----
        if (tid >= DIN_) return;
        __shared__ float xs[DIN_];
        {
            float s[8] = {0.f, 0.f, 0.f, 0.f, 0.f, 0.f, 0.f, 0.f};
#pragma unroll
            for (int seg = 0; seg < NSEG; seg += 8)
#pragma unroll
                for (int j = 0; j < 8; ++j)
                    s[j] += g_xsp[((size_t)(seg + j) * B_ + b) * DIN_ + tid];
            xs[tid] = ((s[0] + s[1]) + (s[2] + s[3])) +
                      ((s[4] + s[5]) + (s[6] + s[7]));
        }
        __syncthreads();
        const int k = tid & 63;
        const int q = tid >> 6;
        float a0 = 0.f, a1 = 0.f, a2 = 0.f, a3 = 0.f;
        const int dbase = q * 64;
#pragma unroll 4
        for (int i = 0; i < 64; i += 4) {
            a0 = fmaf(xs[dbase + i + 0], W_theta[(dbase + i + 0) * K_ + k], a0);
            a1 = fmaf(xs[dbase + i + 1], W_theta[(dbase + i + 1) * K_ + k], a1);
            a2 = fmaf(xs[dbase + i + 2], W_theta[(dbase + i + 2) * K_ + k], a2);
            a3 = fmaf(xs[dbase + i + 3], W_theta[(dbase + i + 3) * K_ + k], a3);
        }
        __shared__ float part[8][K_];
        part[q][k] = (a0 + a1) + (a2 + a3);
        __syncthreads();
        __shared__ float gf[2 * K_];
        if (tid < K_) {
            double acc = 0.0;
#pragma unroll
            for (int r = 0; r < 8; ++r) acc += (double)part[r][tid];
            acc += (double)T_ * (double)b_theta[tid];
            double ang = 3.14159265358979323846 * acc;
            double sn, cs;
            sincos(ang, &sn, &cs);
            gf[tid] = (float)cs;
            gf[K_ + tid] = (float)sn;
        }
        __syncthreads();
        if (tid < 2) {
            float l = b_par[tid];
            for (int j = 0; j < 2 * K_; ++j)
                l += gf[j] * W_par[j * 2 + tid];
            out[b * 2 + tid] = l;
        }
    }
}

// ---------------------------------------------------------------------------
extern "C" void kernel_launch(void* const* d_in, const int* in_sizes, int n_in,
                              void* d_out, int out_size) {
    const float* x       = (const float*)d_in[0];
    const float* W_theta = (const float*)d_in[1];
    const float* b_theta = (const float*)d_in[2];
    const float* W_lam   = (const float*)d_in[3];
    const float* b_lam   = (const float*)d_in[4];
    const float* W_delt  = (const float*)d_in[5];
    const float* b_delt  = (const float*)d_in[6];
    const float* W_inp   = (const float*)d_in[7];
    const float* b_inp   = (const float*)d_in[8];
    const float* W_par   = (const float*)d_in[9];
    const float* b_par   = (const float*)d_in[10];
    const float* W_add   = (const float*)d_in[11];
    const float* b_add   = (const float*)d_in[12];
    float* out = (float*)d_out;

    static int nsm = 0;
    if (!nsm) {
        cudaFuncSetAttribute(gssm_mma_kernel,
                             cudaFuncAttributeMaxDynamicSharedMemorySize,
                             SMEM_BYTES);
        if (cudaDeviceGetAttribute(&nsm, cudaDevAttrMultiProcessorCount, 0)
                != cudaSuccess || nsm <= 0)
            nsm = 148;
    }

    // Prep: fused x convert + partial sums; W transpose
    xprep_kernel<<<dim3(B_, NSEG), 128>>>(x);
    wtsplit_kernel<<<dim3(32, 16, 3), 256>>>(W_lam, W_delt, W_inp);

    // Main fused tensor-core GEMM + scan-reduce (persistent streaming)
    gssm_mma_kernel<<<nsm, NTHREADS, SMEM_BYTES>>>(b_lam, b_delt, b_inp);

    // Heads (combine + parity in one launch)
    heads_kernel<<<dim3(B_, 2), 1024>>>(W_theta, b_theta, W_par, b_par,
                                        W_add, b_add, out);
}

// round 14
// speedup vs baseline: 2.7792x; 1.0117x over previous
#include <cuda_runtime.h>
#include <cuda_fp16.h>
#include <math.h>
#include <stdint.h>

// ---------------------------------------------------------------------------
// GSSM — HMMA fp16, round 14: fully hidden epilogue via acc smem-stash.
// R13 residue: ~0.9us/tile of serial MUFU (acc -> alpha/drive) at each tile
// boundary. Fix: at tile end, stash raw acc to smem (48 conflict-free STS,
// [m][t] stride-132 layout), then convert in 4 slices inside the NEXT tile's
// pair loop (p=0..3), scan_p2 at p=4, scan_p3 at p=5 — all under MMAs, using
// only the existing per-pair barriers. Ring shrunk to 2 pair-slots (depth-1
// prefetch: ~0.7us load vs ~1.6us compute per pair) to fit the stash.
//
// Inputs (metadata order):
//  0: x(32,2048,512) 1: W_theta(512,64) 2: b_theta(64)
//  3: W_lam(512,1024) 4: b_lam 5: W_delt 6: b_delt 7: W_inp 8: b_inp
//  9: W_par(128,2) 10: b_par(2) 11: W_add(1024,1) 12: b_add(1)
// Output: parity_logits (32,2) at [0,64), add_pred (32,1) at [64,96)
// ---------------------------------------------------------------------------

#define B_ 32
#define T_ 2048
#define DIN_ 512
#define M_ 1024
#define K_ 64

#define TB 128               // t rows per tile
#define MB 64                // m cols per tile
#define KC 32                // k per sub-chunk
#define NPAIR 8              // 16 sub-chunks = 8 pairs per tile
#define NTT2 (T_ / TB)       // 16 t-tiles per batch
#define NMB (M_ / MB)        // 16 m-tiles
#define NTILES (NMB * B_ * NTT2)   // 8192
#define NSEG 64              // xs reduction segments (TS = 32)

#define NTHREADS 512

// smem sub-stage layout (fp16, padded rows of 40 elems = 80 B):
//   A: [128 rows][40]  = 10240 B ; B: [3 w][64 rows][40] = 15360 B
#define A_ROW_B 80
#define STAGE_A 10240
#define STAGE_BYTES 25600
#define RING_BYTES (STAGE_BYTES * 4)         // 102400 (2 pair-slots)
#define EPI_OFF RING_BYTES
#define SRS 132                               // sraw stride in floats ([m][t])
#define SRAW_BYTES (64 * SRS * 4)             // 33792 per array
#define SMEM_BYTES (RING_BYTES + 3 * SRAW_BYTES + 4096)   // 207872

// ---- static device scratch (no allocation allowed) ------------------------
__device__ __half g_xh[(size_t)B_ * T_ * DIN_];
__device__ __half g_wh[3u * M_ * DIN_];    // [w][m][k] K-major, fp16
__device__ float g_A[B_ * NTT2 * M_];
__device__ float g_D[B_ * NTT2 * M_];
__device__ float g_xsp[NSEG * B_ * DIN_];  // fp32 partial sums of x over T segs

// ---- helpers ---------------------------------------------------------------
__device__ __forceinline__ uint32_t smem_u32(const void* p) {
    uint32_t a;
    asm("{ .reg .u64 t; cvta.to.shared.u64 t, %1; cvt.u32.u64 %0, t; }"
        : "=r"(a) : "l"(p));
    return a;
}

__device__ __forceinline__ void cp_async16(uint32_t dst, const void* src) {
    asm volatile("cp.async.cg.shared.global [%0], [%1], 16;"
                 :: "r"(dst), "l"(src) : "memory");
}

__device__ __forceinline__ void ldsm_x4(uint32_t* r, uint32_t addr) {
    asm volatile("ldmatrix.sync.aligned.m8n8.x4.shared.b16 {%0,%1,%2,%3}, [%4];"
                 : "=r"(r[0]), "=r"(r[1]), "=r"(r[2]), "=r"(r[3]) : "r"(addr));
}

__device__ __forceinline__ void mma16816(float* d, const uint32_t* a,
                                         const uint32_t* b) {
    asm volatile(
        "mma.sync.aligned.m16n8k16.row.col.f32.f16.f16.f32 "
        "{%0,%1,%2,%3}, {%4,%5,%6,%7}, {%8,%9}, {%0,%1,%2,%3};"
        : "+f"(d[0]), "+f"(d[1]), "+f"(d[2]), "+f"(d[3])
        : "r"(a[0]), "r"(a[1]), "r"(a[2]), "r"(a[3]), "r"(b[0]), "r"(b[1]));
}

// |z| <= ~4 here, so the unstable form is safe
__device__ __forceinline__ float softplus_fast(float z) {
    return __logf(1.0f + __expf(z));
}

// ---------------------------------------------------------------------------
// Prep 1 (fused): x -> fp16, and fp32 partial sums over 64 T-segments.
// ---------------------------------------------------------------------------
__global__ void xprep_kernel(const float* __restrict__ x) {
    const int b = blockIdx.x;
    const int seg = blockIdx.y;
    const int d0 = threadIdx.x * 4;
    const int TS = T_ / NSEG;   // 32
    const float* xp = x + ((size_t)b * T_ + (size_t)seg * TS) * DIN_ + d0;
    __half* hp = g_xh + ((size_t)b * T_ + (size_t)seg * TS) * DIN_ + d0;
    float s0 = 0.f, s1 = 0.f, s2 = 0.f, s3 = 0.f;
#pragma unroll 8
    for (int t = 0; t < TS; ++t) {
        float4 v = *(const float4*)(xp + (size_t)t * DIN_);
        s0 += v.x; s1 += v.y; s2 += v.z; s3 += v.w;
        __align__(8) __half h[4] = {__float2half(v.x), __float2half(v.y),
                                    __float2half(v.z), __float2half(v.w)};
        *(uint2*)(hp + (size_t)t * DIN_) = *(const uint2*)h;
    }
    float4 out = make_float4(s0, s1, s2, s3);
    *(float4*)&g_xsp[((size_t)seg * B_ + b) * DIN_ + d0] = out;
}

// ---------------------------------------------------------------------------
// Prep 2: transpose W (512x1024 f32) -> [w][m][k] fp16
// ---------------------------------------------------------------------------
__global__ void wtsplit_kernel(const float* __restrict__ Wl,
                               const float* __restrict__ Wd,
                               const float* __restrict__ Wi) {
    __shared__ float tile[32][33];
    const int w = blockIdx.z;
    const float* W = (w == 0) ? Wl : ((w == 1) ? Wd : Wi);
    const int m0 = blockIdx.x * 32;
    const int k0 = blockIdx.y * 32;
    const int tx = threadIdx.x & 31;
    const int ty = threadIdx.x >> 5;
#pragma unroll
    for (int r = 0; r < 4; ++r)
        tile[ty + 8 * r][tx] = W[(size_t)(k0 + ty + 8 * r) * M_ + m0 + tx];
    __syncthreads();
#pragma unroll
    for (int r = 0; r < 4; ++r) {
        int m = ty + 8 * r;
        int k = tx;
        size_t o = ((size_t)w * M_ + m0 + m) * DIN_ + k0 + k;
        g_wh[o] = __float2half(tile[k][m]);
    }
}

// ---------------------------------------------------------------------------
// Main persistent kernel.
// ---------------------------------------------------------------------------
__global__ void __launch_bounds__(NTHREADS, 1)
gssm_mma_kernel(const float* __restrict__ b_lam,
                const float* __restrict__ b_delt,
                const float* __restrict__ b_inp) {
    extern __shared__ __align__(128) char smem[];
    const uint32_t sb = smem_u32(smem);
    const int tid = threadIdx.x;
    const int lane = tid & 31;
    const int wid = tid >> 5;
    const int wt = wid & 3;        // t-quadrant: rows wt*32..+31
    const int wm = wid >> 2;       // m-sixteenth: cols wm*16..+15

    // ---- per-thread constant load offsets ----------------------------------
    const size_t constA = (size_t)(tid >> 2) * DIN_ + (size_t)(tid & 3) * 8;
    const uint32_t dstA = sb + (tid >> 2) * A_ROW_B + (tid & 3) * 16;
    size_t constB[2];
    uint32_t dstB[2];
#pragma unroll
    for (int q = 0; q < 2; ++q) {
        int idx = q * NTHREADS + tid;
        int w = idx >> 8;
        int n = (idx >> 2) & 63;
        int v = idx & 3;
        if (w > 2) w = 2;
        constB[q] = ((size_t)w * M_ + n) * DIN_ + (size_t)v * 8;
        dstB[q] = sb + STAGE_A + w * 5120 + n * A_ROW_B + v * 16;
    }
    const bool b1_active = (tid < 256);

    // ---- hoisted ldmatrix row offsets --------------------------------------
    const int rsub = (lane & 7) + 8 * ((lane >> 3) & 1);
    const int ksub2 = 16 * (lane >> 4);
    uint32_t aRow[2];
#pragma unroll
    for (int ts = 0; ts < 2; ++ts)
        aRow[ts] = (uint32_t)((wt * 32 + ts * 16 + rsub) * A_ROW_B) + ksub2;
    const uint32_t bRow =
        (uint32_t)(STAGE_A + (wm * 16 + rsub) * A_ROW_B) + ksub2;

    auto issue_pair = [&](const __half* bA, const __half* bB, int lp, int slot) {
        const uint32_t so0 = (uint32_t)slot * (2 * STAGE_BYTES);
        const size_t ko0 = (size_t)(2 * lp) * KC;
#pragma unroll
        for (int c = 0; c < 2; ++c) {
            const uint32_t so = so0 + c * STAGE_BYTES;
            const size_t ko = ko0 + c * KC;
            cp_async16(dstA + so, bA + constA + ko);
            cp_async16(dstB[0] + so, bB + constB[0] + ko);
            if (b1_active) cp_async16(dstB[1] + so, bB + constB[1] + ko);
        }
        asm volatile("cp.async.commit_group;" ::: "memory");
    };

    float acc[3][2][2][4];

    auto compute = [&](int stg) {
        const uint32_t base = sb + stg * STAGE_BYTES;
#pragma unroll
        for (int kk = 0; kk < 2; ++kk) {
            const uint32_t kb = base + kk * 32;
            uint32_t ah[2][4];
#pragma unroll
            for (int ts = 0; ts < 2; ++ts)
                ldsm_x4(ah[ts], kb + aRow[ts]);
            uint32_t bf[3][2][2];
#pragma unroll
            for (int w = 0; w < 3; ++w) {
                uint32_t r4[4];
                ldsm_x4(r4, kb + w * 5120 + bRow);
                bf[w][0][0] = r4[0];
                bf[w][1][0] = r4[1];
                bf[w][0][1] = r4[2];
                bf[w][1][1] = r4[3];
            }
#pragma unroll
            for (int w = 0; w < 3; ++w)
#pragma unroll
                for (int ts = 0; ts < 2; ++ts)
#pragma unroll
                    for (int nt = 0; nt < 2; ++nt)
                        mma16816(acc[w][ts][nt], ah[ts], bf[w][nt]);
        }
    };

    // ---- epilogue smem: raw stash [m][t] stride SRS; in-place converted ----
    float* sraw_l = (float*)(smem + EPI_OFF);                  // -> alpha
    float* sraw_d = (float*)(smem + EPI_OFF + SRAW_BYTES);     // -> drive
    float* sraw_i = (float*)(smem + EPI_OFF + 2 * SRAW_BYTES);
    float* sAp = (float*)(smem + EPI_OFF + 3 * SRAW_BYTES);        // [8][64]
    float* sDp = (float*)(smem + EPI_OFF + 3 * SRAW_BYTES + 2048); // [8][64]

    float4 bl4, bd4, bi4;   // biases of the stashed (previous) tile

    // stash raw acc for this tile; preload next-needed biases
    auto stash_tile = [&](int m0) {
        bl4 = *(const float4*)&b_lam[m0 + wid * 4];
        bd4 = *(const float4*)&b_delt[m0 + wid * 4];
        bi4 = *(const float4*)&b_inp[m0 + wid * 4];
#pragma unroll
        for (int ts = 0; ts < 2; ++ts)
#pragma unroll
            for (int nt = 0; nt < 2; ++nt)
#pragma unroll
                for (int h = 0; h < 2; ++h)
#pragma unroll
                    for (int c = 0; c < 2; ++c) {
                        const int t = wt * 32 + ts * 16 + h * 8 + (lane >> 2);
                        const int m = wm * 16 + nt * 8 + 2 * (lane & 3) + c;
                        const int o = m * SRS + t;
                        sraw_l[o] = acc[0][ts][nt][h * 2 + c];
                        sraw_d[o] = acc[1][ts][nt][h * 2 + c];
                        sraw_i[o] = acc[2][ts][nt][h * 2 + c];
                    }
    };

    // slice sp (0..3): convert rows [32sp, 32sp+32) of the stashed tile
    auto slice = [&](int sp) {
        const int t = sp * 32 + lane;
        const float* blf = (const float*)&bl4;
        const float* bdf = (const float*)&bd4;
        const float* bif = (const float*)&bi4;
#pragma unroll
        for (int j = 0; j < 4; ++j) {
            const int o = (wid * 4 + j) * SRS + t;
            float zl = sraw_l[o] + blf[j];
            float zd = sraw_d[o] + bdf[j];
            float zi = sraw_i[o] + bif[j];
            float lamv = softplus_fast(zl);
            float dlv = softplus_fast(zd);
            sraw_l[o] = __expf(-dlv * lamv);
            sraw_d[o] = dlv * zi;
        }
    };

    auto scan_p2 = [&]() {
        const int m = tid & 63;
        const int ty = tid >> 6;
        float A = 1.f, D = 0.f;
#pragma unroll
        for (int r = 0; r < 16; ++r) {
            const int o = m * SRS + ty * 16 + r;
            float a = sraw_l[o];
            D = a * D + sraw_d[o];
            A *= a;
        }
        sAp[ty * 64 + m] = A;
        sDp[ty * 64 + m] = D;
    };
    auto scan_p3 = [&](size_t o) {
        if (tid < 64) {
            float A = 1.f, D = 0.f;
#pragma unroll
            for (int r = 0; r < 8; ++r) {
                float a = sAp[r * 64 + tid];
                D = a * D + sDp[r * 64 + tid];
                A *= a;
            }
            g_A[o + tid] = A;
            g_D[o + tid] = D;
        }
    };

    const int GS = gridDim.x;
    int g0 = blockIdx.x;
    if (g0 >= NTILES) return;

    const __half* curA = g_xh + (size_t)(g0 >> 4) * TB * DIN_;
    const __half* curB = g_wh + (size_t)(g0 & 15) * MB * DIN_;
    int sc = 0;
    issue_pair(curA, curB, 0, 0);

    int prev_valid = 0;
    size_t prev_o = 0;

#pragma unroll 1
    for (int g = g0; g < NTILES; g += GS) {
        const int gn = g + GS;
        const bool has_next = (gn < NTILES);
        const __half* nxtA =
            has_next ? g_xh + (size_t)(gn >> 4) * TB * DIN_ : curA;
        const __half* nxtB =
            has_next ? g_wh + (size_t)(gn & 15) * MB * DIN_ : curB;
        const int m0 = (g & 15) * MB;

#pragma unroll
        for (int w = 0; w < 3; ++w)
#pragma unroll
            for (int ts = 0; ts < 2; ++ts)
#pragma unroll
                for (int nt = 0; nt < 2; ++nt)
#pragma unroll
                    for (int f = 0; f < 4; ++f) acc[w][ts][nt][f] = 0.f;

#pragma unroll 1
        for (int p = 0; p < NPAIR; ++p) {
            __syncthreads();
            if (p < 7)
                issue_pair(curA, curB, p + 1, sc ^ 1);
            else if (has_next)
                issue_pair(nxtA, nxtB, 0, sc ^ 1);
            // hidden epilogue of the previous tile (ordered by the syncs)
            if (prev_valid) {
                if (p < 4) slice(p);
                else if (p == 4) scan_p2();
                else if (p == 5) scan_p3(prev_o);
            }
            if (p < 7 || has_next)
                asm volatile("cp.async.wait_group 1;" ::: "memory");
            else
                asm volatile("cp.async.wait_group 0;" ::: "memory");
            compute(sc * 2);
            compute(sc * 2 + 1);
            sc ^= 1;
        }

        // stash this tile's raw acc (no barrier needed: next p=0 sync orders)
        stash_tile(m0);
        prev_valid = 1;
        prev_o = (size_t)(g >> 4) * M_ + m0;
        curA = nxtA;
        curB = nxtB;
    }
    // drain: final tile's epilogue
    __syncthreads();
    slice(0); slice(1); slice(2); slice(3);
    __syncthreads();
    scan_p2();
    __syncthreads();
    scan_p3(prev_o);
}

// ---------------------------------------------------------------------------
// Heads kernel: grid (B_, 2) x 1024 threads.
//  y==0: combine 16 t-tiles per (b,m) -> add_pred[b]
//  y==1: parity path (512 threads)
// ---------------------------------------------------------------------------
__global__ void heads_kernel(const float* __restrict__ W_theta,
                             const float* __restrict__ b_theta,
                             const float* __restrict__ W_par,
                             const float* __restrict__ b_par,
                             const float* __restrict__ W_add,
                             const float* __restrict__ b_add,
                             float* __restrict__ out) {
    const int b = blockIdx.x;
    const int tid = threadIdx.x;
    if (blockIdx.y == 0) {
        int m = tid;
        float s = 0.f;
#pragma unroll
        for (int tt = 0; tt < NTT2; ++tt) {
            size_t idx = ((size_t)(b * NTT2 + tt)) * M_ + m;
            s = g_A[idx] * s + g_D[idx];
        }
        float v = s * W_add[m];
        __shared__ float red[32];
        for (int off = 16; off > 0; off >>= 1)
            v += __shfl_down_sync(0xffffffffu, v, off);
        if ((m & 31) == 0) red[m >> 5] = v;
        __syncthreads();
        if (m < 32) {
            float w = red[m];
            for (int off = 16; off > 0; off >>= 1)
                w += __shfl_down_sync(0xffffffffu, w, off);
            if (m == 0) out[2 * B_ + b] = w + b_add[0];
        }
    } else {
        if (tid >= DIN_) return;
        __shared__ float xs[DIN_];
        {
            float s[8] = {0.f, 0.f, 0.f, 0.f, 0.f, 0.f, 0.f, 0.f};
#pragma unroll
            for (int seg = 0; seg < NSEG; seg += 8)
#pragma unroll
                for (int j = 0; j < 8; ++j)
                    s[j] += g_xsp[((size_t)(seg + j) * B_ + b) * DIN_ + tid];
            xs[tid] = ((s[0] + s[1]) + (s[2] + s[3])) +
                      ((s[4] + s[5]) + (s[6] + s[7]));
        }
        __syncthreads();
        const int k = tid & 63;
        const int q = tid >> 6;
        float a0 = 0.f, a1 = 0.f, a2 = 0.f, a3 = 0.f;
        const int dbase = q * 64;
#pragma unroll 4
        for (int i = 0; i < 64; i += 4) {
            a0 = fmaf(xs[dbase + i + 0], W_theta[(dbase + i + 0) * K_ + k], a0);
            a1 = fmaf(xs[dbase + i + 1], W_theta[(dbase + i + 1) * K_ + k], a1);
            a2 = fmaf(xs[dbase + i + 2], W_theta[(dbase + i + 2) * K_ + k], a2);
            a3 = fmaf(xs[dbase + i + 3], W_theta[(dbase + i + 3) * K_ + k], a3);
        }
        __shared__ float part[8][K_];
        part[q][k] = (a0 + a1) + (a2 + a3);
        __syncthreads();
        __shared__ float gf[2 * K_];
        if (tid < K_) {
            double acc = 0.0;
#pragma unroll
            for (int r = 0; r < 8; ++r) acc += (double)part[r][tid];
            acc += (double)T_ * (double)b_theta[tid];
            double ang = 3.14159265358979323846 * acc;
            double sn, cs;
            sincos(ang, &sn, &cs);
            gf[tid] = (float)cs;
            gf[K_ + tid] = (float)sn;
        }
        __syncthreads();
        if (tid < 2) {
            float l = b_par[tid];
            for (int j = 0; j < 2 * K_; ++j)
                l += gf[j] * W_par[j * 2 + tid];
            out[b * 2 + tid] = l;
        }
    }
}

// ---------------------------------------------------------------------------
extern "C" void kernel_launch(void* const* d_in, const int* in_sizes, int n_in,
                              void* d_out, int out_size) {
    const float* x       = (const float*)d_in[0];
    const float* W_theta = (const float*)d_in[1];
    const float* b_theta = (const float*)d_in[2];
    const float* W_lam   = (const float*)d_in[3];
    const float* b_lam   = (const float*)d_in[4];
    const float* W_delt  = (const float*)d_in[5];
    const float* b_delt  = (const float*)d_in[6];
    const float* W_inp   = (const float*)d_in[7];
    const float* b_inp   = (const float*)d_in[8];
    const float* W_par   = (const float*)d_in[9];
    const float* b_par   = (const float*)d_in[10];
    const float* W_add   = (const float*)d_in[11];
    const float* b_add   = (const float*)d_in[12];
    float* out = (float*)d_out;

    static int nsm = 0;
    if (!nsm) {
        cudaFuncSetAttribute(gssm_mma_kernel,
                             cudaFuncAttributeMaxDynamicSharedMemorySize,
                             SMEM_BYTES);
        if (cudaDeviceGetAttribute(&nsm, cudaDevAttrMultiProcessorCount, 0)
                != cudaSuccess || nsm <= 0)
            nsm = 148;
    }

    // Prep: fused x convert + partial sums; W transpose
    xprep_kernel<<<dim3(B_, NSEG), 128>>>(x);
    wtsplit_kernel<<<dim3(32, 16, 3), 256>>>(W_lam, W_delt, W_inp);

    // Main fused tensor-core GEMM + fully hidden epilogue (persistent)
    gssm_mma_kernel<<<nsm, NTHREADS, SMEM_BYTES>>>(b_lam, b_delt, b_inp);

    // Heads (combine + parity in one launch)
    heads_kernel<<<dim3(B_, 2), 1024>>>(W_theta, b_theta, W_par, b_par,
                                        W_add, b_add, out);
}